// round 15
// baseline (speedup 1.0000x reference)
#include <cuda_runtime.h>
#include <cuda_fp16.h>
#include <math.h>
#include <stdint.h>

#define Bn 32
#define Cc 192
#define WSZ 7
#define NHEAD 6
#define NT 49
#define HIDDEN 768
#define SCALE 0.17677669529663687f
#define ATTN_BLOCKS 2048
#define MLP_BLOCKS 1568

// scratch for x + attention residual
__device__ float g_x2[(size_t)Bn * 56 * 56 * Cc];
// dependency counters: [batch 32][band 8]
__device__ int g_dep[Bn * 8];

// fragment-packed fp16 weights, (n8 x k32) super-tiles of 128 u32:
// lane L holds 4 consecutive u32 at 4*L = {k16#0 b0,b1, k16#1 b0,b1}
// stile index = (n/8)*(K/32) + k/32
__device__ __align__(16) uint32_t g_qkvF[72 * 6 * 128];    // N=576 K=192
__device__ __align__(16) uint32_t g_projF[24 * 6 * 128];   // N=192 K=192
__device__ __align__(16) uint32_t g_fc1F[96 * 6 * 128];    // N=768 K=192
__device__ __align__(16) uint32_t g_fc2F[24 * 24 * 128];   // N=192 K=768
// fused rel-pos bias + shift mask, padded: [win 64][head 6][row 64][col 56]
__device__ __align__(16) __half g_bias[64 * 6 * 64 * 56];

__device__ __forceinline__ uint32_t packh2(float a, float b) {
    __half2 h = __floats2half2_rn(a, b);
    return *(uint32_t*)&h;
}

__global__ void convert_w(const float* __restrict__ qkv_w, const float* __restrict__ proj_w,
                          const float* __restrict__ fc1w, const float* __restrict__ fc2w,
                          const float* __restrict__ mask, const float* __restrict__ rel_table)
{
    int tid = blockIdx.x * blockDim.x + threadIdx.x;
    int stride = gridDim.x * blockDim.x;
    if (tid < Bn * 8) g_dep[tid] = 0;
    // QKV: src [192 k][576 n]
    for (int j = tid; j < 72 * 6 * 128; j += stride) {
        int st = j >> 7, r = j & 127, L = r >> 2, c = r & 3;
        int n = (st / 6) * 8 + (L >> 2);
        int k = (st % 6) * 32 + (c >> 1) * 16 + (c & 1) * 8 + (L & 3) * 2;
        g_qkvF[j] = packh2(qkv_w[k * 576 + n], qkv_w[(k + 1) * 576 + n]);
    }
    // proj: src [192][192]
    for (int j = tid; j < 24 * 6 * 128; j += stride) {
        int st = j >> 7, r = j & 127, L = r >> 2, c = r & 3;
        int n = (st / 6) * 8 + (L >> 2);
        int k = (st % 6) * 32 + (c >> 1) * 16 + (c & 1) * 8 + (L & 3) * 2;
        g_projF[j] = packh2(proj_w[k * 192 + n], proj_w[(k + 1) * 192 + n]);
    }
    // fc1: src [192 k][768 n]
    for (int j = tid; j < 96 * 6 * 128; j += stride) {
        int st = j >> 7, r = j & 127, L = r >> 2, c = r & 3;
        int n = (st / 6) * 8 + (L >> 2);
        int k = (st % 6) * 32 + (c >> 1) * 16 + (c & 1) * 8 + (L & 3) * 2;
        g_fc1F[j] = packh2(fc1w[k * 768 + n], fc1w[(k + 1) * 768 + n]);
    }
    // fc2: src [768 k][192 n]
    for (int j = tid; j < 24 * 24 * 128; j += stride) {
        int st = j >> 7, r = j & 127, L = r >> 2, c = r & 3;
        int n = (st / 24) * 8 + (L >> 2);
        int k = (st % 24) * 32 + (c >> 1) * 16 + (c & 1) * 8 + (L & 3) * 2;
        g_fc2F[j] = packh2(fc2w[k * 192 + n], fc2w[(k + 1) * 192 + n]);
    }
    // bias table, vectorized half2 writes (col pairs)
    for (int j = tid; j < 64 * 6 * 64 * 28; j += stride) {
        int cp = j % 28;
        int rest = j / 28;
        int row = rest % 64; rest /= 64;
        int h = rest % 6;
        int w = rest / 6;
        float v0, v1;
        if (row >= NT) { v0 = 0.f; v1 = 0.f; }
        else {
            int c0 = 2 * cp, c1 = 2 * cp + 1;
            if (c0 >= NT) v0 = -30000.f;
            else {
                int rr = row / 7 - c0 / 7 + 6, cc = row % 7 - c0 % 7 + 6;
                v0 = rel_table[(rr * 13 + cc) * NHEAD + h] + mask[w * 2401 + row * 49 + c0];
            }
            if (c1 >= NT) v1 = -30000.f;
            else {
                int rr = row / 7 - c1 / 7 + 6, cc = row % 7 - c1 % 7 + 6;
                v1 = rel_table[(rr * 13 + cc) * NHEAD + h] + mask[w * 2401 + row * 49 + c1];
            }
        }
        ((__half2*)g_bias)[((size_t)(w * 6 + h) * 64 + row) * 28 + cp] =
            __floats2half2_rn(v0, v1);
    }
}

__device__ __forceinline__ void mma16(float4& c, uint32_t a0, uint32_t a1, uint32_t a2,
                                      uint32_t a3, uint32_t b0, uint32_t b1) {
    asm volatile(
        "mma.sync.aligned.m16n8k16.row.col.f32.f16.f16.f32 "
        "{%0,%1,%2,%3},{%4,%5,%6,%7},{%8,%9},{%0,%1,%2,%3};"
        : "+f"(c.x), "+f"(c.y), "+f"(c.z), "+f"(c.w)
        : "r"(a0), "r"(a1), "r"(a2), "r"(a3), "r"(b0), "r"(b1));
}

__device__ __forceinline__ uint32_t smaddr(const void* p) {
    return (uint32_t)__cvta_generic_to_shared(p);
}

__device__ __forceinline__ void ldsm4(uint32_t& r0, uint32_t& r1, uint32_t& r2,
                                      uint32_t& r3, uint32_t a) {
    asm volatile("ldmatrix.sync.aligned.m8n8.x4.shared.b16 {%0,%1,%2,%3},[%4];"
                 : "=r"(r0), "=r"(r1), "=r"(r2), "=r"(r3) : "r"(a));
}

__device__ __forceinline__ float gelu_exact(float v) {
    return 0.5f * v * (1.0f + erff(v * 0.70710678118654752f));
}

// ---------------------------------------------------------------------------
#define XW_STRH 200
#define QK_STRH 392
#define VT_STRH 72
#define OFF_QK_H 12800        // 64*200
#define OFF_VT_H 34752        // + 56*392
#define FUSED_SM_BYTES (48576 * 2)
#define OFF_HS_H 12800

__device__ __forceinline__ void attn_body(
    __half* smh, int bid,
    const float* __restrict__ x,
    const float* __restrict__ qkv_b, const float* __restrict__ proj_b,
    const float* __restrict__ n1w, const float* __restrict__ n1b)
{
    __half* xwh = smh;                   // [64][200]
    __half* qkh = smh + OFF_QK_H;        // [56][392]
    __half* vth = smh + OFF_VT_H;        // [192][72]
    uint32_t* xwu  = (uint32_t*)xwh;
    uint32_t* vtu  = (uint32_t*)vth;

    const int b    = bid >> 6;
    const int w    = bid & 63;
    const int wh   = w >> 3;
    const int ww   = w & 7;
    const int tid  = threadIdx.x;
    const int warp = tid >> 5;
    const int lane = tid & 31;
    const int g    = lane >> 2;
    const int q    = lane & 3;
    const int wm   = warp & 1;
    const int wn   = warp >> 1;
    const int lr   = lane & 7;
    const int lb8  = (lane >> 3) & 1;
    const int lb16 = lane >> 4;

    const uint32_t aBase = smaddr(xwh + (32 * wm + lr + 8 * lb8) * XW_STRH + 8 * lb16);

    for (int idx = tid; idx < 192 * 36; idx += 256) vtu[idx] = 0u;
    for (int idx = tid; idx < 7 * 196; idx += 256)
        ((uint32_t*)qkh)[(49 + idx / 196) * 196 + idx % 196] = 0u;

    // ---- Phase 1: gather + LN1 ----
    for (int n = warp; n < 64; n += 8) {
        if (n < NT) {
            int r  = wh * WSZ + n / WSZ;
            int c  = ww * WSZ + n % WSZ;
            int gr = r + 3; if (gr >= 56) gr -= 56;
            int gc = c + 3; if (gc >= 56) gc -= 56;
            const float* xr = x + ((size_t)b * 3136 + gr * 56 + gc) * Cc;
            float v[6]; float s = 0.f, ss = 0.f;
#pragma unroll
            for (int j = 0; j < 6; j++) { v[j] = xr[lane + 32 * j]; s += v[j]; ss += v[j] * v[j]; }
#pragma unroll
            for (int o = 16; o > 0; o >>= 1) {
                s  += __shfl_xor_sync(0xffffffffu, s,  o);
                ss += __shfl_xor_sync(0xffffffffu, ss, o);
            }
            float mean = s * (1.f / 192.f);
            float rinv = rsqrtf(ss * (1.f / 192.f) - mean * mean + 1e-5f);
#pragma unroll
            for (int j = 0; j < 6; j++) {
                int k = lane + 32 * j;
                xwh[n * XW_STRH + k] = __float2half((v[j] - mean) * rinv * n1w[k] + n1b[k]);
            }
        } else {
#pragma unroll
            for (int j = 0; j < 3; j++) xwu[n * 100 + lane + 32 * j] = 0u;
        }
    }
    __syncthreads();

    // ---- Phase 2: QKV, uint4 B-fragments from gmem ----
    for (int p = 0; p < 3; p++) {
        float4 acc[2][6];
#pragma unroll
        for (int mf = 0; mf < 2; mf++)
#pragma unroll
            for (int t = 0; t < 6; t++) acc[mf][t] = make_float4(0.f, 0.f, 0.f, 0.f);

        const int sb = (24 * p + 6 * wn) * 6;
        uint4 bn[6];
#pragma unroll
        for (int tp = 0; tp < 6; tp++)
            bn[tp] = *(const uint4*)(g_qkvF + (size_t)(sb + tp * 6) * 128 + 4 * lane);

#pragma unroll
        for (int kc = 0; kc < 6; kc++) {
            uint4 bc[6];
#pragma unroll
            for (int tp = 0; tp < 6; tp++) bc[tp] = bn[tp];
            if (kc < 5) {
#pragma unroll
                for (int tp = 0; tp < 6; tp++)
                    bn[tp] = *(const uint4*)(g_qkvF + (size_t)(sb + tp * 6 + kc + 1) * 128 + 4 * lane);
            } else if (p < 2) {
                const int sb2 = (24 * (p + 1) + 6 * wn) * 6;
#pragma unroll
                for (int tp = 0; tp < 6; tp++)
                    bn[tp] = *(const uint4*)(g_qkvF + (size_t)(sb2 + tp * 6) * 128 + 4 * lane);
            }
#pragma unroll
            for (int ss = 0; ss < 2; ss++) {
                uint32_t a[2][4];
                ldsm4(a[0][0], a[0][1], a[0][2], a[0][3], aBase + 64 * kc + 32 * ss);
                ldsm4(a[1][0], a[1][1], a[1][2], a[1][3], aBase + 6400 + 64 * kc + 32 * ss);
#pragma unroll
                for (int tp = 0; tp < 6; tp++) {
                    uint32_t b0 = ss ? bc[tp].z : bc[tp].x;
                    uint32_t b1 = ss ? bc[tp].w : bc[tp].y;
#pragma unroll
                    for (int mf = 0; mf < 2; mf++)
                        mma16(acc[mf][tp], a[mf][0], a[mf][1], a[mf][2], a[mf][3], b0, b1);
                }
            }
        }
#pragma unroll
        for (int mf = 0; mf < 2; mf++) {
            int r0 = 32 * wm + 16 * mf + g;
            bool u0 = r0 < NT, u1 = (r0 + 8) < NT;
#pragma unroll
            for (int t = 0; t < 6; t++) {
                int col = 48 * wn + 8 * t + 2 * q;
                int j   = 192 * p + col;
                float b0v = __ldg(qkv_b + j), b1v = __ldg(qkv_b + j + 1);
                float o00 = acc[mf][t].x + b0v, o01 = acc[mf][t].y + b1v;
                float o10 = acc[mf][t].z + b0v, o11 = acc[mf][t].w + b1v;
                if (p == 0) { o00 *= SCALE; o01 *= SCALE; o10 *= SCALE; o11 *= SCALE; }
                if (p < 2) {
                    if (u0) *(__half2*)(qkh + r0 * QK_STRH + j)       = __floats2half2_rn(o00, o01);
                    if (u1) *(__half2*)(qkh + (r0 + 8) * QK_STRH + j) = __floats2half2_rn(o10, o11);
                } else {
                    if (u0) {
                        vth[col * VT_STRH + r0]       = __float2half(o00);
                        vth[(col + 1) * VT_STRH + r0] = __float2half(o01);
                    }
                    if (u1) {
                        vth[col * VT_STRH + r0 + 8]       = __float2half(o10);
                        vth[(col + 1) * VT_STRH + r0 + 8] = __float2half(o11);
                    }
                }
            }
        }
    }
    __syncthreads();

    // ---- Phase 3: mma attention, 24 units, 3 per warp ----
    {
#pragma unroll 1
        for (int t = 0; t < 3; t++) {
            const int u = warp * 3 + t;
            const int h = u >> 2;
            const int i = u & 3;
            const __half* bias = g_bias + ((size_t)(w * NHEAD + h)) * 64 * 56;
            const uint32_t kBase = smaddr(qkh + lr * QK_STRH + 192 + h * 32 + 8 * (lane >> 3));
            const uint32_t vBase = smaddr(vth + (h * 32 + lr) * VT_STRH + 8 * (lane >> 3));
            const int r0i = 16 * i + g, r1i = r0i + 8;

            float2 bb0[7], bb1[7];
#pragma unroll
            for (int j = 0; j < 7; j++) {
                bb0[j] = __half22float2(*(const __half2*)(bias + r0i * 56 + 8 * j + 2 * q));
                bb1[j] = __half22float2(*(const __half2*)(bias + r1i * 56 + 8 * j + 2 * q));
            }

            uint32_t qA = smaddr(qkh + (16 * i + lr + 8 * lb8) * QK_STRH + h * 32 + 8 * lb16);
            uint32_t aq[2][4];
            ldsm4(aq[0][0], aq[0][1], aq[0][2], aq[0][3], qA);
            ldsm4(aq[1][0], aq[1][1], aq[1][2], aq[1][3], qA + 32);
            float4 S[7];
#pragma unroll
            for (int j = 0; j < 7; j++) {
                S[j] = make_float4(0.f, 0.f, 0.f, 0.f);
                uint32_t b0, b1, b2, b3;
                ldsm4(b0, b1, b2, b3, kBase + j * (8 * QK_STRH * 2));
                mma16(S[j], aq[0][0], aq[0][1], aq[0][2], aq[0][3], b0, b1);
                mma16(S[j], aq[1][0], aq[1][1], aq[1][2], aq[1][3], b2, b3);
                S[j].x += bb0[j].x; S[j].y += bb0[j].y;
                S[j].z += bb1[j].x; S[j].w += bb1[j].y;
            }
            float mx0 = -1e30f, mx1 = -1e30f;
#pragma unroll
            for (int j = 0; j < 7; j++) {
                mx0 = fmaxf(mx0, fmaxf(S[j].x, S[j].y));
                mx1 = fmaxf(mx1, fmaxf(S[j].z, S[j].w));
            }
#pragma unroll
            for (int o = 1; o < 4; o <<= 1) {
                mx0 = fmaxf(mx0, __shfl_xor_sync(0xffffffffu, mx0, o));
                mx1 = fmaxf(mx1, __shfl_xor_sync(0xffffffffu, mx1, o));
            }
            float sum0 = 0.f, sum1 = 0.f;
#pragma unroll
            for (int j = 0; j < 7; j++) {
                S[j].x = __expf(S[j].x - mx0); S[j].y = __expf(S[j].y - mx0);
                S[j].z = __expf(S[j].z - mx1); S[j].w = __expf(S[j].w - mx1);
                sum0 += S[j].x + S[j].y; sum1 += S[j].z + S[j].w;
            }
#pragma unroll
            for (int o = 1; o < 4; o <<= 1) {
                sum0 += __shfl_xor_sync(0xffffffffu, sum0, o);
                sum1 += __shfl_xor_sync(0xffffffffu, sum1, o);
            }
            float rc0 = 1.f / sum0, rc1 = 1.f / sum1;
            uint32_t pa[4][4];
#pragma unroll
            for (int kk = 0; kk < 3; kk++) {
                pa[kk][0] = packh2(S[2 * kk].x, S[2 * kk].y);
                pa[kk][1] = packh2(S[2 * kk].z, S[2 * kk].w);
                pa[kk][2] = packh2(S[2 * kk + 1].x, S[2 * kk + 1].y);
                pa[kk][3] = packh2(S[2 * kk + 1].z, S[2 * kk + 1].w);
            }
            pa[3][0] = packh2(S[6].x, S[6].y);
            pa[3][1] = packh2(S[6].z, S[6].w);
            pa[3][2] = 0u; pa[3][3] = 0u;
            float4 O[4];
#pragma unroll
            for (int vj = 0; vj < 4; vj++) {
                O[vj] = make_float4(0.f, 0.f, 0.f, 0.f);
                uint32_t va0, va1, va2, va3, vb0, vb1, vb2, vb3;
                ldsm4(va0, va1, va2, va3, vBase + vj * (8 * VT_STRH * 2));
                ldsm4(vb0, vb1, vb2, vb3, vBase + vj * (8 * VT_STRH * 2) + 64);
                mma16(O[vj], pa[0][0], pa[0][1], pa[0][2], pa[0][3], va0, va1);
                mma16(O[vj], pa[1][0], pa[1][1], pa[1][2], pa[1][3], va2, va3);
                mma16(O[vj], pa[2][0], pa[2][1], pa[2][2], pa[2][3], vb0, vb1);
                mma16(O[vj], pa[3][0], pa[3][1], pa[3][2], pa[3][3], vb2, vb3);
            }
#pragma unroll
            for (int vj = 0; vj < 4; vj++) {
                int col = h * 32 + 8 * vj + 2 * q;
                if (r0i < NT)
                    *(__half2*)(xwh + r0i * XW_STRH + col) =
                        __floats2half2_rn(O[vj].x * rc0, O[vj].y * rc0);
                if (r1i < NT)
                    *(__half2*)(xwh + r1i * XW_STRH + col) =
                        __floats2half2_rn(O[vj].z * rc1, O[vj].w * rc1);
            }
        }
    }
    __syncthreads();

    // ---- Phase 4: proj, uint4 B-fragments, fused residual scatter ----
    {
        float4 acc[2][6];
#pragma unroll
        for (int mf = 0; mf < 2; mf++)
#pragma unroll
            for (int t = 0; t < 6; t++) acc[mf][t] = make_float4(0.f, 0.f, 0.f, 0.f);

        const int sb = (6 * wn) * 6;
        uint4 bn[6];
#pragma unroll
        for (int tp = 0; tp < 6; tp++)
            bn[tp] = *(const uint4*)(g_projF + (size_t)(sb + tp * 6) * 128 + 4 * lane);

#pragma unroll
        for (int kc = 0; kc < 6; kc++) {
            uint4 bc[6];
#pragma unroll
            for (int tp = 0; tp < 6; tp++) bc[tp] = bn[tp];
            if (kc < 5) {
#pragma unroll
                for (int tp = 0; tp < 6; tp++)
                    bn[tp] = *(const uint4*)(g_projF + (size_t)(sb + tp * 6 + kc + 1) * 128 + 4 * lane);
            }
#pragma unroll
            for (int ss = 0; ss < 2; ss++) {
                uint32_t a[2][4];
                ldsm4(a[0][0], a[0][1], a[0][2], a[0][3], aBase + 64 * kc + 32 * ss);
                ldsm4(a[1][0], a[1][1], a[1][2], a[1][3], aBase + 6400 + 64 * kc + 32 * ss);
#pragma unroll
                for (int tp = 0; tp < 6; tp++) {
                    uint32_t b0 = ss ? bc[tp].z : bc[tp].x;
                    uint32_t b1 = ss ? bc[tp].w : bc[tp].y;
#pragma unroll
                    for (int mf = 0; mf < 2; mf++)
                        mma16(acc[mf][tp], a[mf][0], a[mf][1], a[mf][2], a[mf][3], b0, b1);
                }
            }
        }

#pragma unroll
        for (int mf = 0; mf < 2; mf++) {
            int r0 = 32 * wm + 16 * mf + g;
            bool u0 = r0 < NT, u1 = (r0 + 8) < NT;
            size_t base0 = 0, base1 = 0;
            if (u0) {
                int gr = wh * 7 + r0 / 7 + 3; if (gr >= 56) gr -= 56;
                int gc = ww * 7 + r0 % 7 + 3; if (gc >= 56) gc -= 56;
                base0 = ((size_t)b * 3136 + gr * 56 + gc) * Cc;
            }
            if (u1) {
                int r1 = r0 + 8;
                int gr = wh * 7 + r1 / 7 + 3; if (gr >= 56) gr -= 56;
                int gc = ww * 7 + r1 % 7 + 3; if (gc >= 56) gc -= 56;
                base1 = ((size_t)b * 3136 + gr * 56 + gc) * Cc;
            }
#pragma unroll
            for (int t = 0; t < 6; t++) {
                int col = 48 * wn + 8 * t + 2 * q;
                float pb0 = __ldg(proj_b + col), pb1 = __ldg(proj_b + col + 1);
                if (u0) {
                    float2 xv = *(const float2*)(x + base0 + col);
                    float2 r; r.x = xv.x + acc[mf][t].x + pb0; r.y = xv.y + acc[mf][t].y + pb1;
                    *(float2*)(g_x2 + base0 + col) = r;
                }
                if (u1) {
                    float2 xv = *(const float2*)(x + base1 + col);
                    float2 r; r.x = xv.x + acc[mf][t].z + pb0; r.y = xv.y + acc[mf][t].w + pb1;
                    *(float2*)(g_x2 + base1 + col) = r;
                }
            }
        }
    }

    __threadfence();
    __syncthreads();
    if (tid == 0) atomicAdd(&g_dep[b * 8 + wh], 1);
}

__device__ __forceinline__ void mlp_body(
    __half* smh, int m,
    const float* __restrict__ n2w, const float* __restrict__ n2b,
    const float* __restrict__ fc1b, const float* __restrict__ fc2b,
    float* __restrict__ out)
{
    __half* xnh = smh;                       // [64][200]
    __half* hsh = smh + OFF_HS_H;            // [64][200] hidden chunk (192 cols)
    __half2* hs2 = (__half2*)hsh;

    const int tid  = threadIdx.x;
    const int warp = tid >> 5;
    const int lane = tid & 31;
    const int g    = lane >> 2;
    const int q    = lane & 3;
    const int wm   = warp & 1;      // m-half (32 rows) for fc1 AND fc2
    const int wn   = warp >> 1;     // n-quarter (48 cols) for fc1 AND fc2
    const int lr   = lane & 7;
    const int lb8  = (lane >> 3) & 1;
    const int lb16 = lane >> 4;
    const size_t t0 = (size_t)m * 64;

    const uint32_t aBase1 = smaddr(xnh + (32 * wm + lr + 8 * lb8) * XW_STRH + 8 * lb16);
    const uint32_t aBase2 = smaddr(hsh + (32 * wm + lr + 8 * lb8) * XW_STRH + 8 * lb16);

    // ---- acquire ----
    {
        int mm = m % 49;
        int bb = m / 49;
        int gr0 = (mm * 64) / 56;
        int gr1 = (mm * 64 + 63) / 56;
        int i0 = bb * 8 + ((gr0 + 53) % 56) / 7;
        int i1 = bb * 8 + ((gr1 + 53) % 56) / 7;
        if (tid == 0) {
            while (atomicAdd(&g_dep[i0], 0) < 8 || atomicAdd(&g_dep[i1], 0) < 8)
                __nanosleep(100);
        }
        __syncthreads();
    }

    // ---- LN2 ----
    for (int n = warp; n < 64; n += 8) {
        const float* xr = g_x2 + (t0 + n) * Cc;
        float v[6]; float s = 0.f, ss = 0.f;
#pragma unroll
        for (int j = 0; j < 6; j++) { v[j] = xr[lane + 32 * j]; s += v[j]; ss += v[j] * v[j]; }
#pragma unroll
        for (int o = 16; o > 0; o >>= 1) {
            s  += __shfl_xor_sync(0xffffffffu, s,  o);
            ss += __shfl_xor_sync(0xffffffffu, ss, o);
        }
        float mean = s * (1.f / 192.f);
        float rinv = rsqrtf(ss * (1.f / 192.f) - mean * mean + 1e-5f);
#pragma unroll
        for (int j = 0; j < 6; j++) {
            int k = lane + 32 * j;
            xnh[n * XW_STRH + k] = __float2half((v[j] - mean) * rinv * n2w[k] + n2b[k]);
        }
    }
    __syncthreads();

    float4 yacc[2][6];
#pragma unroll
    for (int mf = 0; mf < 2; mf++)
#pragma unroll
        for (int t = 0; t < 6; t++) yacc[mf][t] = make_float4(0.f, 0.f, 0.f, 0.f);

    for (int hc = 0; hc < HIDDEN; hc += 192) {
        // ---- fc1: H(64x192) = xn @ w1chunk ; warp tile m32 x n48 ----
        float4 acc1[2][6];
#pragma unroll
        for (int mf = 0; mf < 2; mf++)
#pragma unroll
            for (int t = 0; t < 6; t++) acc1[mf][t] = make_float4(0.f, 0.f, 0.f, 0.f);

        const int sb1 = ((hc >> 3) + 6 * wn) * 6;
        uint4 b1n[6];
#pragma unroll
        for (int t = 0; t < 6; t++)
            b1n[t] = *(const uint4*)(g_fc1F + (size_t)(sb1 + t * 6) * 128 + 4 * lane);

#pragma unroll
        for (int kc = 0; kc < 6; kc++) {
            uint4 b1c[6];
#pragma unroll
            for (int t = 0; t < 6; t++) b1c[t] = b1n[t];
            if (kc < 5) {
#pragma unroll
                for (int t = 0; t < 6; t++)
                    b1n[t] = *(const uint4*)(g_fc1F + (size_t)(sb1 + t * 6 + kc + 1) * 128 + 4 * lane);
            }
#pragma unroll
            for (int ss = 0; ss < 2; ss++) {
                uint32_t a[2][4];
                ldsm4(a[0][0], a[0][1], a[0][2], a[0][3], aBase1 + 64 * kc + 32 * ss);
                ldsm4(a[1][0], a[1][1], a[1][2], a[1][3], aBase1 + 6400 + 64 * kc + 32 * ss);
#pragma unroll
                for (int t = 0; t < 6; t++) {
                    uint32_t b0 = ss ? b1c[t].z : b1c[t].x;
                    uint32_t b1 = ss ? b1c[t].w : b1c[t].y;
#pragma unroll
                    for (int mf = 0; mf < 2; mf++)
                        mma16(acc1[mf][t], a[mf][0], a[mf][1], a[mf][2], a[mf][3], b0, b1);
                }
            }
        }

        // prefetch fc2 first k32 of this chunk
        const int t2k = hc >> 5;   // 6 k32-steps per chunk
        uint4 b2n[6];
#pragma unroll
        for (int tp = 0; tp < 6; tp++)
            b2n[tp] = *(const uint4*)(g_fc2F + (size_t)((6 * wn + tp) * 24 + t2k) * 128 + 4 * lane);

        __syncthreads();   // previous fc2 done reading hs
        // bias + gelu -> hs (chunk cols 0..191 at stride 200)
#pragma unroll
        for (int mf = 0; mf < 2; mf++) {
            int rF = 32 * wm + 16 * mf + g;
#pragma unroll
            for (int t = 0; t < 6; t++) {
                int col = 48 * wn + 8 * t + 2 * q;
                float b0v = __ldg(fc1b + hc + col), b1v = __ldg(fc1b + hc + col + 1);
                int wi = 24 * wn + 4 * t + q;   // half2 index (stride 100)
                hs2[rF * 100 + wi]       = __floats2half2_rn(gelu_exact(acc1[mf][t].x + b0v),
                                                             gelu_exact(acc1[mf][t].y + b1v));
                hs2[(rF + 8) * 100 + wi] = __floats2half2_rn(gelu_exact(acc1[mf][t].z + b0v),
                                                             gelu_exact(acc1[mf][t].w + b1v));
            }
        }
        __syncthreads();   // hs ready

        // ---- fc2: Y += H @ w2chunk ; warp tile m32 x n48, 6 k32 steps ----
#pragma unroll
        for (int kc = 0; kc < 6; kc++) {
            uint4 b2c[6];
#pragma unroll
            for (int tp = 0; tp < 6; tp++) b2c[tp] = b2n[tp];
            if (kc < 5) {
#pragma unroll
                for (int tp = 0; tp < 6; tp++)
                    b2n[tp] = *(const uint4*)(g_fc2F + (size_t)((6 * wn + tp) * 24 + t2k + kc + 1) * 128 + 4 * lane);
            }
#pragma unroll
            for (int ss = 0; ss < 2; ss++) {
                uint32_t a[2][4];
                ldsm4(a[0][0], a[0][1], a[0][2], a[0][3], aBase2 + 64 * kc + 32 * ss);
                ldsm4(a[1][0], a[1][1], a[1][2], a[1][3], aBase2 + 6400 + 64 * kc + 32 * ss);
#pragma unroll
                for (int tp = 0; tp < 6; tp++) {
                    uint32_t b0 = ss ? b2c[tp].z : b2c[tp].x;
                    uint32_t b1 = ss ? b2c[tp].w : b2c[tp].y;
#pragma unroll
                    for (int mf = 0; mf < 2; mf++)
                        mma16(yacc[mf][tp], a[mf][0], a[mf][1], a[mf][2], a[mf][3], b0, b1);
                }
            }
        }
    }

#pragma unroll
    for (int mf = 0; mf < 2; mf++) {
        int r0 = 32 * wm + 16 * mf + g;
#pragma unroll
        for (int t = 0; t < 6; t++) {
            int col = 48 * wn + 8 * t + 2 * q;
            float b0v = __ldg(fc2b + col), b1v = __ldg(fc2b + col + 1);
            {
                size_t base = (t0 + r0) * Cc + col;
                float2 xv = *(const float2*)(g_x2 + base);
                float2 r; r.x = xv.x + yacc[mf][t].x + b0v; r.y = xv.y + yacc[mf][t].y + b1v;
                *(float2*)(out + base) = r;
            }
            {
                size_t base = (t0 + r0 + 8) * Cc + col;
                float2 xv = *(const float2*)(g_x2 + base);
                float2 r; r.x = xv.x + yacc[mf][t].z + b0v; r.y = xv.y + yacc[mf][t].w + b1v;
                *(float2*)(out + base) = r;
            }
        }
    }
}

__global__ __launch_bounds__(256, 2) void swin_fused_kernel(
    const float* __restrict__ x,
    const float* __restrict__ qkv_b, const float* __restrict__ proj_b,
    const float* __restrict__ n1w, const float* __restrict__ n1b,
    const float* __restrict__ n2w, const float* __restrict__ n2b,
    const float* __restrict__ fc1b, const float* __restrict__ fc2b,
    float* __restrict__ out)
{
    extern __shared__ __half smh[];
    const int bid = blockIdx.x;
    if (bid < ATTN_BLOCKS) {
        attn_body(smh, bid, x, qkv_b, proj_b, n1w, n1b);
    } else {
        mlp_body(smh, bid - ATTN_BLOCKS, n2w, n2b, fc1b, fc2b, out);
    }
}

// ---------------------------------------------------------------------------
extern "C" void kernel_launch(void* const* d_in, const int* in_sizes, int n_in,
                              void* d_out, int out_size)
{
    const float* x      = (const float*)d_in[0];
    const float* mask   = (const float*)d_in[1];
    const float* rel    = (const float*)d_in[2];
    const float* qkv_w  = (const float*)d_in[3];
    const float* qkv_b  = (const float*)d_in[4];
    const float* proj_w = (const float*)d_in[5];
    const float* proj_b = (const float*)d_in[6];
    const float* n1w    = (const float*)d_in[7];
    const float* n1b    = (const float*)d_in[8];
    const float* n2w    = (const float*)d_in[9];
    const float* n2b    = (const float*)d_in[10];
    const float* fc1w   = (const float*)d_in[11];
    const float* fc1b   = (const float*)d_in[12];
    const float* fc2w   = (const float*)d_in[13];
    const float* fc2b   = (const float*)d_in[14];
    float* out = (float*)d_out;

    cudaFuncSetAttribute(swin_fused_kernel, cudaFuncAttributeMaxDynamicSharedMemorySize,
                         FUSED_SM_BYTES);

    convert_w<<<1184, 256>>>(qkv_w, proj_w, fc1w, fc2w, mask, rel);
    swin_fused_kernel<<<ATTN_BLOCKS + MLP_BLOCKS, 256, FUSED_SM_BYTES>>>(
        x, qkv_b, proj_b, n1w, n1b, n2w, n2b, fc1b, fc2b, out);
}

// round 16
// speedup vs baseline: 1.0866x; 1.0866x over previous
#include <cuda_runtime.h>
#include <cuda_fp16.h>
#include <math.h>
#include <stdint.h>

#define Bn 32
#define Cc 192
#define WSZ 7
#define NHEAD 6
#define NT 49
#define HIDDEN 768
#define SCALE 0.17677669529663687f
#define ATTN_BLOCKS 2048
#define MLP_BLOCKS 1568

// scratch for x + attention residual
__device__ float g_x2[(size_t)Bn * 56 * 56 * Cc];
// dependency counters: [batch 32][band 8]
__device__ int g_dep[Bn * 8];

// fragment-packed fp16 weights, (n8 x k32) super-tiles of 128 u32:
// lane L holds 4 consecutive u32 at 4*L = {k16#0 b0,b1, k16#1 b0,b1}
// stile index = (n/8)*(K/32) + k/32
__device__ __align__(16) uint32_t g_qkvF[72 * 6 * 128];    // N=576 K=192
__device__ __align__(16) uint32_t g_projF[24 * 6 * 128];   // N=192 K=192
__device__ __align__(16) uint32_t g_fc1F[96 * 6 * 128];    // N=768 K=192
__device__ __align__(16) uint32_t g_fc2F[24 * 24 * 128];   // N=192 K=768
// fused rel-pos bias + shift mask, padded: [win 64][head 6][row 64][col 56]
__device__ __align__(16) __half g_bias[64 * 6 * 64 * 56];

__device__ __forceinline__ uint32_t packh2(float a, float b) {
    __half2 h = __floats2half2_rn(a, b);
    return *(uint32_t*)&h;
}

__global__ void convert_w(const float* __restrict__ qkv_w, const float* __restrict__ proj_w,
                          const float* __restrict__ fc1w, const float* __restrict__ fc2w,
                          const float* __restrict__ mask, const float* __restrict__ rel_table)
{
    int tid = blockIdx.x * blockDim.x + threadIdx.x;
    int stride = gridDim.x * blockDim.x;
    if (tid < Bn * 8) g_dep[tid] = 0;
    // QKV: src [192 k][576 n]
    for (int j = tid; j < 72 * 6 * 128; j += stride) {
        int st = j >> 7, r = j & 127, L = r >> 2, c = r & 3;
        int n = (st / 6) * 8 + (L >> 2);
        int k = (st % 6) * 32 + (c >> 1) * 16 + (c & 1) * 8 + (L & 3) * 2;
        g_qkvF[j] = packh2(qkv_w[k * 576 + n], qkv_w[(k + 1) * 576 + n]);
    }
    // proj: src [192][192]
    for (int j = tid; j < 24 * 6 * 128; j += stride) {
        int st = j >> 7, r = j & 127, L = r >> 2, c = r & 3;
        int n = (st / 6) * 8 + (L >> 2);
        int k = (st % 6) * 32 + (c >> 1) * 16 + (c & 1) * 8 + (L & 3) * 2;
        g_projF[j] = packh2(proj_w[k * 192 + n], proj_w[(k + 1) * 192 + n]);
    }
    // fc1: src [192 k][768 n]
    for (int j = tid; j < 96 * 6 * 128; j += stride) {
        int st = j >> 7, r = j & 127, L = r >> 2, c = r & 3;
        int n = (st / 6) * 8 + (L >> 2);
        int k = (st % 6) * 32 + (c >> 1) * 16 + (c & 1) * 8 + (L & 3) * 2;
        g_fc1F[j] = packh2(fc1w[k * 768 + n], fc1w[(k + 1) * 768 + n]);
    }
    // fc2: src [768 k][192 n]
    for (int j = tid; j < 24 * 24 * 128; j += stride) {
        int st = j >> 7, r = j & 127, L = r >> 2, c = r & 3;
        int n = (st / 24) * 8 + (L >> 2);
        int k = (st % 24) * 32 + (c >> 1) * 16 + (c & 1) * 8 + (L & 3) * 2;
        g_fc2F[j] = packh2(fc2w[k * 192 + n], fc2w[(k + 1) * 192 + n]);
    }
    // bias table, vectorized half2 writes (col pairs)
    for (int j = tid; j < 64 * 6 * 64 * 28; j += stride) {
        int cp = j % 28;
        int rest = j / 28;
        int row = rest % 64; rest /= 64;
        int h = rest % 6;
        int w = rest / 6;
        float v0, v1;
        if (row >= NT) { v0 = 0.f; v1 = 0.f; }
        else {
            int c0 = 2 * cp, c1 = 2 * cp + 1;
            if (c0 >= NT) v0 = -30000.f;
            else {
                int rr = row / 7 - c0 / 7 + 6, cc = row % 7 - c0 % 7 + 6;
                v0 = rel_table[(rr * 13 + cc) * NHEAD + h] + mask[w * 2401 + row * 49 + c0];
            }
            if (c1 >= NT) v1 = -30000.f;
            else {
                int rr = row / 7 - c1 / 7 + 6, cc = row % 7 - c1 % 7 + 6;
                v1 = rel_table[(rr * 13 + cc) * NHEAD + h] + mask[w * 2401 + row * 49 + c1];
            }
        }
        ((__half2*)g_bias)[((size_t)(w * 6 + h) * 64 + row) * 28 + cp] =
            __floats2half2_rn(v0, v1);
    }
}

__device__ __forceinline__ void mma16(float4& c, uint32_t a0, uint32_t a1, uint32_t a2,
                                      uint32_t a3, uint32_t b0, uint32_t b1) {
    asm volatile(
        "mma.sync.aligned.m16n8k16.row.col.f32.f16.f16.f32 "
        "{%0,%1,%2,%3},{%4,%5,%6,%7},{%8,%9},{%0,%1,%2,%3};"
        : "+f"(c.x), "+f"(c.y), "+f"(c.z), "+f"(c.w)
        : "r"(a0), "r"(a1), "r"(a2), "r"(a3), "r"(b0), "r"(b1));
}

__device__ __forceinline__ uint32_t smaddr(const void* p) {
    return (uint32_t)__cvta_generic_to_shared(p);
}

__device__ __forceinline__ void ldsm4(uint32_t& r0, uint32_t& r1, uint32_t& r2,
                                      uint32_t& r3, uint32_t a) {
    asm volatile("ldmatrix.sync.aligned.m8n8.x4.shared.b16 {%0,%1,%2,%3},[%4];"
                 : "=r"(r0), "=r"(r1), "=r"(r2), "=r"(r3) : "r"(a));
}

__device__ __forceinline__ float gelu_exact(float v) {
    return 0.5f * v * (1.0f + erff(v * 0.70710678118654752f));
}

// ---------------------------------------------------------------------------
#define XW_STRH 200
#define QK_STRH 392
#define VT_STRH 72
#define HS_STRH 136
#define OFF_QK_H 12800        // 64*200
#define OFF_VT_H 34752        // + 56*392
#define FUSED_SM_BYTES (48576 * 2)
#define OFF_HS_H 12800

__device__ __forceinline__ void attn_body(
    __half* smh, int bid,
    const float* __restrict__ x,
    const float* __restrict__ qkv_b, const float* __restrict__ proj_b,
    const float* __restrict__ n1w, const float* __restrict__ n1b)
{
    __half* xwh = smh;                   // [64][200]
    __half* qkh = smh + OFF_QK_H;        // [56][392]
    __half* vth = smh + OFF_VT_H;        // [192][72]
    uint32_t* xwu  = (uint32_t*)xwh;
    uint32_t* vtu  = (uint32_t*)vth;

    const int b    = bid >> 6;
    const int w    = bid & 63;
    const int wh   = w >> 3;
    const int ww   = w & 7;
    const int tid  = threadIdx.x;
    const int warp = tid >> 5;
    const int lane = tid & 31;
    const int g    = lane >> 2;
    const int q    = lane & 3;
    const int wm   = warp & 1;
    const int wn   = warp >> 1;
    const int lr   = lane & 7;
    const int lb8  = (lane >> 3) & 1;
    const int lb16 = lane >> 4;

    const uint32_t aBase = smaddr(xwh + (32 * wm + lr + 8 * lb8) * XW_STRH + 8 * lb16);

    for (int idx = tid; idx < 192 * 36; idx += 256) vtu[idx] = 0u;
    for (int idx = tid; idx < 7 * 196; idx += 256)
        ((uint32_t*)qkh)[(49 + idx / 196) * 196 + idx % 196] = 0u;

    // ---- Phase 1: gather + LN1 ----
    for (int n = warp; n < 64; n += 8) {
        if (n < NT) {
            int r  = wh * WSZ + n / WSZ;
            int c  = ww * WSZ + n % WSZ;
            int gr = r + 3; if (gr >= 56) gr -= 56;
            int gc = c + 3; if (gc >= 56) gc -= 56;
            const float* xr = x + ((size_t)b * 3136 + gr * 56 + gc) * Cc;
            float v[6]; float s = 0.f, ss = 0.f;
#pragma unroll
            for (int j = 0; j < 6; j++) { v[j] = xr[lane + 32 * j]; s += v[j]; ss += v[j] * v[j]; }
#pragma unroll
            for (int o = 16; o > 0; o >>= 1) {
                s  += __shfl_xor_sync(0xffffffffu, s,  o);
                ss += __shfl_xor_sync(0xffffffffu, ss, o);
            }
            float mean = s * (1.f / 192.f);
            float rinv = rsqrtf(ss * (1.f / 192.f) - mean * mean + 1e-5f);
#pragma unroll
            for (int j = 0; j < 6; j++) {
                int k = lane + 32 * j;
                xwh[n * XW_STRH + k] = __float2half((v[j] - mean) * rinv * n1w[k] + n1b[k]);
            }
        } else {
#pragma unroll
            for (int j = 0; j < 3; j++) xwu[n * 100 + lane + 32 * j] = 0u;
        }
    }
    __syncthreads();

    // ---- Phase 2: QKV, uint4 B-fragments from gmem ----
    for (int p = 0; p < 3; p++) {
        float4 acc[2][6];
#pragma unroll
        for (int mf = 0; mf < 2; mf++)
#pragma unroll
            for (int t = 0; t < 6; t++) acc[mf][t] = make_float4(0.f, 0.f, 0.f, 0.f);

        const int sb = (24 * p + 6 * wn) * 6;
        uint4 bn[6];
#pragma unroll
        for (int tp = 0; tp < 6; tp++)
            bn[tp] = *(const uint4*)(g_qkvF + (size_t)(sb + tp * 6) * 128 + 4 * lane);

#pragma unroll
        for (int kc = 0; kc < 6; kc++) {
            uint4 bc[6];
#pragma unroll
            for (int tp = 0; tp < 6; tp++) bc[tp] = bn[tp];
            if (kc < 5) {
#pragma unroll
                for (int tp = 0; tp < 6; tp++)
                    bn[tp] = *(const uint4*)(g_qkvF + (size_t)(sb + tp * 6 + kc + 1) * 128 + 4 * lane);
            } else if (p < 2) {
                const int sb2 = (24 * (p + 1) + 6 * wn) * 6;
#pragma unroll
                for (int tp = 0; tp < 6; tp++)
                    bn[tp] = *(const uint4*)(g_qkvF + (size_t)(sb2 + tp * 6) * 128 + 4 * lane);
            }
#pragma unroll
            for (int ss = 0; ss < 2; ss++) {
                uint32_t a[2][4];
                ldsm4(a[0][0], a[0][1], a[0][2], a[0][3], aBase + 64 * kc + 32 * ss);
                ldsm4(a[1][0], a[1][1], a[1][2], a[1][3], aBase + 6400 + 64 * kc + 32 * ss);
#pragma unroll
                for (int tp = 0; tp < 6; tp++) {
                    uint32_t b0 = ss ? bc[tp].z : bc[tp].x;
                    uint32_t b1 = ss ? bc[tp].w : bc[tp].y;
#pragma unroll
                    for (int mf = 0; mf < 2; mf++)
                        mma16(acc[mf][tp], a[mf][0], a[mf][1], a[mf][2], a[mf][3], b0, b1);
                }
            }
        }
#pragma unroll
        for (int mf = 0; mf < 2; mf++) {
            int r0 = 32 * wm + 16 * mf + g;
            bool u0 = r0 < NT, u1 = (r0 + 8) < NT;
#pragma unroll
            for (int t = 0; t < 6; t++) {
                int col = 48 * wn + 8 * t + 2 * q;
                int j   = 192 * p + col;
                float b0v = __ldg(qkv_b + j), b1v = __ldg(qkv_b + j + 1);
                float o00 = acc[mf][t].x + b0v, o01 = acc[mf][t].y + b1v;
                float o10 = acc[mf][t].z + b0v, o11 = acc[mf][t].w + b1v;
                if (p == 0) { o00 *= SCALE; o01 *= SCALE; o10 *= SCALE; o11 *= SCALE; }
                if (p < 2) {
                    if (u0) *(__half2*)(qkh + r0 * QK_STRH + j)       = __floats2half2_rn(o00, o01);
                    if (u1) *(__half2*)(qkh + (r0 + 8) * QK_STRH + j) = __floats2half2_rn(o10, o11);
                } else {
                    if (u0) {
                        vth[col * VT_STRH + r0]       = __float2half(o00);
                        vth[(col + 1) * VT_STRH + r0] = __float2half(o01);
                    }
                    if (u1) {
                        vth[col * VT_STRH + r0 + 8]       = __float2half(o10);
                        vth[(col + 1) * VT_STRH + r0 + 8] = __float2half(o11);
                    }
                }
            }
        }
    }
    __syncthreads();

    // ---- Phase 3: mma attention, 24 units, 3 per warp ----
    {
#pragma unroll 1
        for (int t = 0; t < 3; t++) {
            const int u = warp * 3 + t;
            const int h = u >> 2;
            const int i = u & 3;
            const __half* bias = g_bias + ((size_t)(w * NHEAD + h)) * 64 * 56;
            const uint32_t kBase = smaddr(qkh + lr * QK_STRH + 192 + h * 32 + 8 * (lane >> 3));
            const uint32_t vBase = smaddr(vth + (h * 32 + lr) * VT_STRH + 8 * (lane >> 3));
            const int r0i = 16 * i + g, r1i = r0i + 8;

            float2 bb0[7], bb1[7];
#pragma unroll
            for (int j = 0; j < 7; j++) {
                bb0[j] = __half22float2(*(const __half2*)(bias + r0i * 56 + 8 * j + 2 * q));
                bb1[j] = __half22float2(*(const __half2*)(bias + r1i * 56 + 8 * j + 2 * q));
            }

            uint32_t qA = smaddr(qkh + (16 * i + lr + 8 * lb8) * QK_STRH + h * 32 + 8 * lb16);
            uint32_t aq[2][4];
            ldsm4(aq[0][0], aq[0][1], aq[0][2], aq[0][3], qA);
            ldsm4(aq[1][0], aq[1][1], aq[1][2], aq[1][3], qA + 32);
            float4 S[7];
#pragma unroll
            for (int j = 0; j < 7; j++) {
                S[j] = make_float4(0.f, 0.f, 0.f, 0.f);
                uint32_t b0, b1, b2, b3;
                ldsm4(b0, b1, b2, b3, kBase + j * (8 * QK_STRH * 2));
                mma16(S[j], aq[0][0], aq[0][1], aq[0][2], aq[0][3], b0, b1);
                mma16(S[j], aq[1][0], aq[1][1], aq[1][2], aq[1][3], b2, b3);
                S[j].x += bb0[j].x; S[j].y += bb0[j].y;
                S[j].z += bb1[j].x; S[j].w += bb1[j].y;
            }
            float mx0 = -1e30f, mx1 = -1e30f;
#pragma unroll
            for (int j = 0; j < 7; j++) {
                mx0 = fmaxf(mx0, fmaxf(S[j].x, S[j].y));
                mx1 = fmaxf(mx1, fmaxf(S[j].z, S[j].w));
            }
#pragma unroll
            for (int o = 1; o < 4; o <<= 1) {
                mx0 = fmaxf(mx0, __shfl_xor_sync(0xffffffffu, mx0, o));
                mx1 = fmaxf(mx1, __shfl_xor_sync(0xffffffffu, mx1, o));
            }
            float sum0 = 0.f, sum1 = 0.f;
#pragma unroll
            for (int j = 0; j < 7; j++) {
                S[j].x = __expf(S[j].x - mx0); S[j].y = __expf(S[j].y - mx0);
                S[j].z = __expf(S[j].z - mx1); S[j].w = __expf(S[j].w - mx1);
                sum0 += S[j].x + S[j].y; sum1 += S[j].z + S[j].w;
            }
#pragma unroll
            for (int o = 1; o < 4; o <<= 1) {
                sum0 += __shfl_xor_sync(0xffffffffu, sum0, o);
                sum1 += __shfl_xor_sync(0xffffffffu, sum1, o);
            }
            float rc0 = 1.f / sum0, rc1 = 1.f / sum1;
            uint32_t pa[4][4];
#pragma unroll
            for (int kk = 0; kk < 3; kk++) {
                pa[kk][0] = packh2(S[2 * kk].x, S[2 * kk].y);
                pa[kk][1] = packh2(S[2 * kk].z, S[2 * kk].w);
                pa[kk][2] = packh2(S[2 * kk + 1].x, S[2 * kk + 1].y);
                pa[kk][3] = packh2(S[2 * kk + 1].z, S[2 * kk + 1].w);
            }
            pa[3][0] = packh2(S[6].x, S[6].y);
            pa[3][1] = packh2(S[6].z, S[6].w);
            pa[3][2] = 0u; pa[3][3] = 0u;
            float4 O[4];
#pragma unroll
            for (int vj = 0; vj < 4; vj++) {
                O[vj] = make_float4(0.f, 0.f, 0.f, 0.f);
                uint32_t va0, va1, va2, va3, vb0, vb1, vb2, vb3;
                ldsm4(va0, va1, va2, va3, vBase + vj * (8 * VT_STRH * 2));
                ldsm4(vb0, vb1, vb2, vb3, vBase + vj * (8 * VT_STRH * 2) + 64);
                mma16(O[vj], pa[0][0], pa[0][1], pa[0][2], pa[0][3], va0, va1);
                mma16(O[vj], pa[1][0], pa[1][1], pa[1][2], pa[1][3], va2, va3);
                mma16(O[vj], pa[2][0], pa[2][1], pa[2][2], pa[2][3], vb0, vb1);
                mma16(O[vj], pa[3][0], pa[3][1], pa[3][2], pa[3][3], vb2, vb3);
            }
#pragma unroll
            for (int vj = 0; vj < 4; vj++) {
                int col = h * 32 + 8 * vj + 2 * q;
                if (r0i < NT)
                    *(__half2*)(xwh + r0i * XW_STRH + col) =
                        __floats2half2_rn(O[vj].x * rc0, O[vj].y * rc0);
                if (r1i < NT)
                    *(__half2*)(xwh + r1i * XW_STRH + col) =
                        __floats2half2_rn(O[vj].z * rc1, O[vj].w * rc1);
            }
        }
    }
    __syncthreads();

    // ---- Phase 4: proj, uint4 B-fragments, fused residual scatter ----
    {
        float4 acc[2][6];
#pragma unroll
        for (int mf = 0; mf < 2; mf++)
#pragma unroll
            for (int t = 0; t < 6; t++) acc[mf][t] = make_float4(0.f, 0.f, 0.f, 0.f);

        const int sb = (6 * wn) * 6;
        uint4 bn[6];
#pragma unroll
        for (int tp = 0; tp < 6; tp++)
            bn[tp] = *(const uint4*)(g_projF + (size_t)(sb + tp * 6) * 128 + 4 * lane);

#pragma unroll
        for (int kc = 0; kc < 6; kc++) {
            uint4 bc[6];
#pragma unroll
            for (int tp = 0; tp < 6; tp++) bc[tp] = bn[tp];
            if (kc < 5) {
#pragma unroll
                for (int tp = 0; tp < 6; tp++)
                    bn[tp] = *(const uint4*)(g_projF + (size_t)(sb + tp * 6 + kc + 1) * 128 + 4 * lane);
            }
#pragma unroll
            for (int ss = 0; ss < 2; ss++) {
                uint32_t a[2][4];
                ldsm4(a[0][0], a[0][1], a[0][2], a[0][3], aBase + 64 * kc + 32 * ss);
                ldsm4(a[1][0], a[1][1], a[1][2], a[1][3], aBase + 6400 + 64 * kc + 32 * ss);
#pragma unroll
                for (int tp = 0; tp < 6; tp++) {
                    uint32_t b0 = ss ? bc[tp].z : bc[tp].x;
                    uint32_t b1 = ss ? bc[tp].w : bc[tp].y;
#pragma unroll
                    for (int mf = 0; mf < 2; mf++)
                        mma16(acc[mf][tp], a[mf][0], a[mf][1], a[mf][2], a[mf][3], b0, b1);
                }
            }
        }

#pragma unroll
        for (int mf = 0; mf < 2; mf++) {
            int r0 = 32 * wm + 16 * mf + g;
            bool u0 = r0 < NT, u1 = (r0 + 8) < NT;
            size_t base0 = 0, base1 = 0;
            if (u0) {
                int gr = wh * 7 + r0 / 7 + 3; if (gr >= 56) gr -= 56;
                int gc = ww * 7 + r0 % 7 + 3; if (gc >= 56) gc -= 56;
                base0 = ((size_t)b * 3136 + gr * 56 + gc) * Cc;
            }
            if (u1) {
                int r1 = r0 + 8;
                int gr = wh * 7 + r1 / 7 + 3; if (gr >= 56) gr -= 56;
                int gc = ww * 7 + r1 % 7 + 3; if (gc >= 56) gc -= 56;
                base1 = ((size_t)b * 3136 + gr * 56 + gc) * Cc;
            }
#pragma unroll
            for (int t = 0; t < 6; t++) {
                int col = 48 * wn + 8 * t + 2 * q;
                float pb0 = __ldg(proj_b + col), pb1 = __ldg(proj_b + col + 1);
                if (u0) {
                    float2 xv = *(const float2*)(x + base0 + col);
                    float2 r; r.x = xv.x + acc[mf][t].x + pb0; r.y = xv.y + acc[mf][t].y + pb1;
                    *(float2*)(g_x2 + base0 + col) = r;
                }
                if (u1) {
                    float2 xv = *(const float2*)(x + base1 + col);
                    float2 r; r.x = xv.x + acc[mf][t].z + pb0; r.y = xv.y + acc[mf][t].w + pb1;
                    *(float2*)(g_x2 + base1 + col) = r;
                }
            }
        }
    }

    __threadfence();
    __syncthreads();
    if (tid == 0) atomicAdd(&g_dep[b * 8 + wh], 1);
}

__device__ __forceinline__ void mlp_body(
    __half* smh, int m,
    const float* __restrict__ n2w, const float* __restrict__ n2b,
    const float* __restrict__ fc1b, const float* __restrict__ fc2b,
    float* __restrict__ out)
{
    __half* xnh = smh;                       // [64][200]
    __half* hsh = smh + OFF_HS_H;            // [64][136]
    __half2* hs2 = (__half2*)hsh;

    const int tid  = threadIdx.x;
    const int warp = tid >> 5;
    const int lane = tid & 31;
    const int g    = lane >> 2;
    const int q    = lane & 3;
    const int wm   = warp & 1;      // fc2 m-half
    const int wn   = warp >> 1;     // fc2 n-quarter (48 cols)
    const int wm1  = warp >> 2;     // fc1 m-half (32 rows)
    const int wn1  = warp & 3;      // fc1 n-32 block within 128-chunk
    const int lr   = lane & 7;
    const int lb8  = (lane >> 3) & 1;
    const int lb16 = lane >> 4;
    const size_t t0 = (size_t)m * 64;

    const uint32_t aBase1 = smaddr(xnh + (32 * wm1 + lr + 8 * lb8) * XW_STRH + 8 * lb16);
    const uint32_t aBase2 = smaddr(hsh + (32 * wm + lr + 8 * lb8) * HS_STRH + 8 * lb16);

    // ---- acquire ----
    {
        int mm = m % 49;
        int bb = m / 49;
        int gr0 = (mm * 64) / 56;
        int gr1 = (mm * 64 + 63) / 56;
        int i0 = bb * 8 + ((gr0 + 53) % 56) / 7;
        int i1 = bb * 8 + ((gr1 + 53) % 56) / 7;
        if (tid == 0) {
            while (atomicAdd(&g_dep[i0], 0) < 8 || atomicAdd(&g_dep[i1], 0) < 8)
                __nanosleep(100);
        }
        __syncthreads();
    }

    // ---- LN2 ----
    for (int n = warp; n < 64; n += 8) {
        const float* xr = g_x2 + (t0 + n) * Cc;
        float v[6]; float s = 0.f, ss = 0.f;
#pragma unroll
        for (int j = 0; j < 6; j++) { v[j] = xr[lane + 32 * j]; s += v[j]; ss += v[j] * v[j]; }
#pragma unroll
        for (int o = 16; o > 0; o >>= 1) {
            s  += __shfl_xor_sync(0xffffffffu, s,  o);
            ss += __shfl_xor_sync(0xffffffffu, ss, o);
        }
        float mean = s * (1.f / 192.f);
        float rinv = rsqrtf(ss * (1.f / 192.f) - mean * mean + 1e-5f);
#pragma unroll
        for (int j = 0; j < 6; j++) {
            int k = lane + 32 * j;
            xnh[n * XW_STRH + k] = __float2half((v[j] - mean) * rinv * n2w[k] + n2b[k]);
        }
    }
    __syncthreads();

    float4 yacc[2][6];
#pragma unroll
    for (int mf = 0; mf < 2; mf++)
#pragma unroll
        for (int t = 0; t < 6; t++) yacc[mf][t] = make_float4(0.f, 0.f, 0.f, 0.f);

    for (int hc = 0; hc < HIDDEN; hc += 128) {
        // ---- fc1: H(64x128) = xn @ w1chunk ; warp tile m32 x n32 ----
        float4 acc1[2][4];
#pragma unroll
        for (int mf = 0; mf < 2; mf++)
#pragma unroll
            for (int t = 0; t < 4; t++) acc1[mf][t] = make_float4(0.f, 0.f, 0.f, 0.f);

        const int sb1 = ((hc >> 3) + 4 * wn1) * 6;
        uint4 b1n[4];
#pragma unroll
        for (int t = 0; t < 4; t++)
            b1n[t] = *(const uint4*)(g_fc1F + (size_t)(sb1 + t * 6) * 128 + 4 * lane);

#pragma unroll
        for (int kc = 0; kc < 6; kc++) {
            uint4 b1c[4];
#pragma unroll
            for (int t = 0; t < 4; t++) b1c[t] = b1n[t];
            if (kc < 5) {
#pragma unroll
                for (int t = 0; t < 4; t++)
                    b1n[t] = *(const uint4*)(g_fc1F + (size_t)(sb1 + t * 6 + kc + 1) * 128 + 4 * lane);
            }
#pragma unroll
            for (int ss = 0; ss < 2; ss++) {
                uint32_t a[2][4];
                ldsm4(a[0][0], a[0][1], a[0][2], a[0][3], aBase1 + 64 * kc + 32 * ss);
                ldsm4(a[1][0], a[1][1], a[1][2], a[1][3], aBase1 + 6400 + 64 * kc + 32 * ss);
#pragma unroll
                for (int t = 0; t < 4; t++) {
                    uint32_t b0 = ss ? b1c[t].z : b1c[t].x;
                    uint32_t b1 = ss ? b1c[t].w : b1c[t].y;
#pragma unroll
                    for (int mf = 0; mf < 2; mf++)
                        mma16(acc1[mf][t], a[mf][0], a[mf][1], a[mf][2], a[mf][3], b0, b1);
                }
            }
        }

        // prefetch fc2 first k32 of this chunk
        const int t2k = hc >> 5;
        uint4 b2n[6];
#pragma unroll
        for (int tp = 0; tp < 6; tp++)
            b2n[tp] = *(const uint4*)(g_fc2F + (size_t)((6 * wn + tp) * 24 + t2k) * 128 + 4 * lane);

        __syncthreads();   // previous fc2 done reading hs
        // bias + gelu -> hs
#pragma unroll
        for (int mf = 0; mf < 2; mf++) {
            int rF = 32 * wm1 + 16 * mf + g;
#pragma unroll
            for (int t = 0; t < 4; t++) {
                int col = 32 * wn1 + 8 * t + 2 * q;
                float b0v = __ldg(fc1b + hc + col), b1v = __ldg(fc1b + hc + col + 1);
                int wi = 16 * wn1 + 4 * t + q;
                hs2[rF * 68 + wi]       = __floats2half2_rn(gelu_exact(acc1[mf][t].x + b0v),
                                                            gelu_exact(acc1[mf][t].y + b1v));
                hs2[(rF + 8) * 68 + wi] = __floats2half2_rn(gelu_exact(acc1[mf][t].z + b0v),
                                                            gelu_exact(acc1[mf][t].w + b1v));
            }
        }
        __syncthreads();   // hs ready

        // ---- fc2: Y += H @ w2chunk ; warp tile m32 x n48, 4 k32 steps ----
#pragma unroll
        for (int kc = 0; kc < 4; kc++) {
            uint4 b2c[6];
#pragma unroll
            for (int tp = 0; tp < 6; tp++) b2c[tp] = b2n[tp];
            if (kc < 3) {
#pragma unroll
                for (int tp = 0; tp < 6; tp++)
                    b2n[tp] = *(const uint4*)(g_fc2F + (size_t)((6 * wn + tp) * 24 + t2k + kc + 1) * 128 + 4 * lane);
            }
#pragma unroll
            for (int ss = 0; ss < 2; ss++) {
                uint32_t a[2][4];
                ldsm4(a[0][0], a[0][1], a[0][2], a[0][3], aBase2 + 64 * kc + 32 * ss);
                ldsm4(a[1][0], a[1][1], a[1][2], a[1][3], aBase2 + 4352 + 64 * kc + 32 * ss);
#pragma unroll
                for (int tp = 0; tp < 6; tp++) {
                    uint32_t b0 = ss ? b2c[tp].z : b2c[tp].x;
                    uint32_t b1 = ss ? b2c[tp].w : b2c[tp].y;
#pragma unroll
                    for (int mf = 0; mf < 2; mf++)
                        mma16(yacc[mf][tp], a[mf][0], a[mf][1], a[mf][2], a[mf][3], b0, b1);
                }
            }
        }
    }

#pragma unroll
    for (int mf = 0; mf < 2; mf++) {
        int r0 = 32 * wm + 16 * mf + g;
#pragma unroll
        for (int t = 0; t < 6; t++) {
            int col = 48 * wn + 8 * t + 2 * q;
            float b0v = __ldg(fc2b + col), b1v = __ldg(fc2b + col + 1);
            {
                size_t base = (t0 + r0) * Cc + col;
                float2 xv = *(const float2*)(g_x2 + base);
                float2 r; r.x = xv.x + yacc[mf][t].x + b0v; r.y = xv.y + yacc[mf][t].y + b1v;
                *(float2*)(out + base) = r;
            }
            {
                size_t base = (t0 + r0 + 8) * Cc + col;
                float2 xv = *(const float2*)(g_x2 + base);
                float2 r; r.x = xv.x + yacc[mf][t].z + b0v; r.y = xv.y + yacc[mf][t].w + b1v;
                *(float2*)(out + base) = r;
            }
        }
    }
}

__global__ __launch_bounds__(256, 2) void swin_fused_kernel(
    const float* __restrict__ x,
    const float* __restrict__ qkv_b, const float* __restrict__ proj_b,
    const float* __restrict__ n1w, const float* __restrict__ n1b,
    const float* __restrict__ n2w, const float* __restrict__ n2b,
    const float* __restrict__ fc1b, const float* __restrict__ fc2b,
    float* __restrict__ out)
{
    extern __shared__ __half smh[];
    const int bid = blockIdx.x;
    if (bid < ATTN_BLOCKS) {
        attn_body(smh, bid, x, qkv_b, proj_b, n1w, n1b);
    } else {
        mlp_body(smh, bid - ATTN_BLOCKS, n2w, n2b, fc1b, fc2b, out);
    }
}

// ---------------------------------------------------------------------------
extern "C" void kernel_launch(void* const* d_in, const int* in_sizes, int n_in,
                              void* d_out, int out_size)
{
    const float* x      = (const float*)d_in[0];
    const float* mask   = (const float*)d_in[1];
    const float* rel    = (const float*)d_in[2];
    const float* qkv_w  = (const float*)d_in[3];
    const float* qkv_b  = (const float*)d_in[4];
    const float* proj_w = (const float*)d_in[5];
    const float* proj_b = (const float*)d_in[6];
    const float* n1w    = (const float*)d_in[7];
    const float* n1b    = (const float*)d_in[8];
    const float* n2w    = (const float*)d_in[9];
    const float* n2b    = (const float*)d_in[10];
    const float* fc1w   = (const float*)d_in[11];
    const float* fc1b   = (const float*)d_in[12];
    const float* fc2w   = (const float*)d_in[13];
    const float* fc2b   = (const float*)d_in[14];
    float* out = (float*)d_out;

    cudaFuncSetAttribute(swin_fused_kernel, cudaFuncAttributeMaxDynamicSharedMemorySize,
                         FUSED_SM_BYTES);

    convert_w<<<1184, 256>>>(qkv_w, proj_w, fc1w, fc2w, mask, rel);
    swin_fused_kernel<<<ATTN_BLOCKS + MLP_BLOCKS, 256, FUSED_SM_BYTES>>>(
        x, qkv_b, proj_b, n1w, n1b, n2w, n2b, fc1b, fc2b, out);
}

// round 17
// speedup vs baseline: 1.1042x; 1.0162x over previous
#include <cuda_runtime.h>
#include <cuda_fp16.h>
#include <math.h>
#include <stdint.h>

#define Bn 32
#define Cc 192
#define WSZ 7
#define NHEAD 6
#define NT 49
#define HIDDEN 768
#define SCALE 0.17677669529663687f
#define ATTN_BLOCKS 2048
#define MLP_BLOCKS 1568

// scratch for x + attention residual
__device__ float g_x2[(size_t)Bn * 56 * 56 * Cc];
// dependency counters: [batch 32][band 8]
__device__ int g_dep[Bn * 8];

// fragment-packed fp16 weights, (n8 x k32) super-tiles of 128 u32
__device__ __align__(16) uint32_t g_qkvF[72 * 6 * 128];    // N=576 K=192
__device__ __align__(16) uint32_t g_projF[24 * 6 * 128];   // N=192 K=192
__device__ __align__(16) uint32_t g_fc1F[96 * 6 * 128];    // N=768 K=192
__device__ __align__(16) uint32_t g_fc2F[24 * 24 * 128];   // N=192 K=768
// fused rel-pos bias + shift mask, padded: [win 64][head 6][row 64][col 56]
__device__ __align__(16) __half g_bias[64 * 6 * 64 * 56];

__device__ __forceinline__ uint32_t packh2(float a, float b) {
    __half2 h = __floats2half2_rn(a, b);
    return *(uint32_t*)&h;
}

__global__ void convert_w(const float* __restrict__ qkv_w, const float* __restrict__ proj_w,
                          const float* __restrict__ fc1w, const float* __restrict__ fc2w,
                          const float* __restrict__ mask, const float* __restrict__ rel_table)
{
    int tid = blockIdx.x * blockDim.x + threadIdx.x;
    int stride = gridDim.x * blockDim.x;
    if (tid < Bn * 8) g_dep[tid] = 0;
    for (int j = tid; j < 72 * 6 * 128; j += stride) {
        int st = j >> 7, r = j & 127, L = r >> 2, c = r & 3;
        int n = (st / 6) * 8 + (L >> 2);
        int k = (st % 6) * 32 + (c >> 1) * 16 + (c & 1) * 8 + (L & 3) * 2;
        g_qkvF[j] = packh2(qkv_w[k * 576 + n], qkv_w[(k + 1) * 576 + n]);
    }
    for (int j = tid; j < 24 * 6 * 128; j += stride) {
        int st = j >> 7, r = j & 127, L = r >> 2, c = r & 3;
        int n = (st / 6) * 8 + (L >> 2);
        int k = (st % 6) * 32 + (c >> 1) * 16 + (c & 1) * 8 + (L & 3) * 2;
        g_projF[j] = packh2(proj_w[k * 192 + n], proj_w[(k + 1) * 192 + n]);
    }
    for (int j = tid; j < 96 * 6 * 128; j += stride) {
        int st = j >> 7, r = j & 127, L = r >> 2, c = r & 3;
        int n = (st / 6) * 8 + (L >> 2);
        int k = (st % 6) * 32 + (c >> 1) * 16 + (c & 1) * 8 + (L & 3) * 2;
        g_fc1F[j] = packh2(fc1w[k * 768 + n], fc1w[(k + 1) * 768 + n]);
    }
    for (int j = tid; j < 24 * 24 * 128; j += stride) {
        int st = j >> 7, r = j & 127, L = r >> 2, c = r & 3;
        int n = (st / 24) * 8 + (L >> 2);
        int k = (st % 24) * 32 + (c >> 1) * 16 + (c & 1) * 8 + (L & 3) * 2;
        g_fc2F[j] = packh2(fc2w[k * 192 + n], fc2w[(k + 1) * 192 + n]);
    }
    for (int j = tid; j < 64 * 6 * 64 * 28; j += stride) {
        int cp = j % 28;
        int rest = j / 28;
        int row = rest % 64; rest /= 64;
        int h = rest % 6;
        int w = rest / 6;
        float v0, v1;
        if (row >= NT) { v0 = 0.f; v1 = 0.f; }
        else {
            int c0 = 2 * cp, c1 = 2 * cp + 1;
            if (c0 >= NT) v0 = -30000.f;
            else {
                int rr = row / 7 - c0 / 7 + 6, cc = row % 7 - c0 % 7 + 6;
                v0 = rel_table[(rr * 13 + cc) * NHEAD + h] + mask[w * 2401 + row * 49 + c0];
            }
            if (c1 >= NT) v1 = -30000.f;
            else {
                int rr = row / 7 - c1 / 7 + 6, cc = row % 7 - c1 % 7 + 6;
                v1 = rel_table[(rr * 13 + cc) * NHEAD + h] + mask[w * 2401 + row * 49 + c1];
            }
        }
        ((__half2*)g_bias)[((size_t)(w * 6 + h) * 64 + row) * 28 + cp] =
            __floats2half2_rn(v0, v1);
    }
}

__device__ __forceinline__ void mma16(float4& c, uint32_t a0, uint32_t a1, uint32_t a2,
                                      uint32_t a3, uint32_t b0, uint32_t b1) {
    asm volatile(
        "mma.sync.aligned.m16n8k16.row.col.f32.f16.f16.f32 "
        "{%0,%1,%2,%3},{%4,%5,%6,%7},{%8,%9},{%0,%1,%2,%3};"
        : "+f"(c.x), "+f"(c.y), "+f"(c.z), "+f"(c.w)
        : "r"(a0), "r"(a1), "r"(a2), "r"(a3), "r"(b0), "r"(b1));
}

__device__ __forceinline__ uint32_t smaddr(const void* p) {
    return (uint32_t)__cvta_generic_to_shared(p);
}

__device__ __forceinline__ void ldsm4(uint32_t& r0, uint32_t& r1, uint32_t& r2,
                                      uint32_t& r3, uint32_t a) {
    asm volatile("ldmatrix.sync.aligned.m8n8.x4.shared.b16 {%0,%1,%2,%3},[%4];"
                 : "=r"(r0), "=r"(r1), "=r"(r2), "=r"(r3) : "r"(a));
}

__device__ __forceinline__ void stsm4(uint32_t a, uint32_t r0, uint32_t r1,
                                      uint32_t r2, uint32_t r3) {
    asm volatile("stmatrix.sync.aligned.m8n8.x4.shared.b16 [%0], {%1,%2,%3,%4};"
                 :: "r"(a), "r"(r0), "r"(r1), "r"(r2), "r"(r3));
}

__device__ __forceinline__ void stsm4t(uint32_t a, uint32_t r0, uint32_t r1,
                                       uint32_t r2, uint32_t r3) {
    asm volatile("stmatrix.sync.aligned.m8n8.x4.trans.shared.b16 [%0], {%1,%2,%3,%4};"
                 :: "r"(a), "r"(r0), "r"(r1), "r"(r2), "r"(r3));
}

__device__ __forceinline__ float gelu_exact(float v) {
    return 0.5f * v * (1.0f + erff(v * 0.70710678118654752f));
}

// ---------------------------------------------------------------------------
#define XW_STRH 200
#define QK_STRH 392
#define VT_STRH 72
#define HS_STRH 136
#define OFF_QK_H 12800        // 64*200
#define OFF_VT_H 37888        // + 64*392
#define FUSED_SM_BYTES (51712 * 2)
#define OFF_HS_H 12800

__device__ __forceinline__ void attn_body(
    __half* smh, int bid,
    const float* __restrict__ x,
    const float* __restrict__ qkv_b, const float* __restrict__ proj_b,
    const float* __restrict__ n1w, const float* __restrict__ n1b)
{
    __half* xwh = smh;                   // [64][200]
    __half* qkh = smh + OFF_QK_H;        // [64][392] Q(0..191) K(192..383)
    __half* vth = smh + OFF_VT_H;        // [192][72] V transposed
    uint32_t* xwu = (uint32_t*)xwh;

    const int b    = bid >> 6;
    const int w    = bid & 63;
    const int wh   = w >> 3;
    const int ww   = w & 7;
    const int tid  = threadIdx.x;
    const int warp = tid >> 5;
    const int lane = tid & 31;
    const int g    = lane >> 2;
    const int q    = lane & 3;
    const int wm   = warp & 1;
    const int wn   = warp >> 1;
    const int lr   = lane & 7;
    const int lb8  = (lane >> 3) & 1;
    const int lb16 = lane >> 4;
    const int tl   = lane >> 3;      // stmatrix tile id
    const int rw   = lane & 7;       // stmatrix row-in-tile

    const uint32_t aBase = smaddr(xwh + (32 * wm + lr + 8 * lb8) * XW_STRH + 8 * lb16);

    // ---- Phase 1: gather + LN1 (xw rows>=49 zeroed; no K/V zeroing needed) ----
    for (int n = warp; n < 64; n += 8) {
        if (n < NT) {
            int r  = wh * WSZ + n / WSZ;
            int c  = ww * WSZ + n % WSZ;
            int gr = r + 3; if (gr >= 56) gr -= 56;
            int gc = c + 3; if (gc >= 56) gc -= 56;
            const float* xr = x + ((size_t)b * 3136 + gr * 56 + gc) * Cc;
            float v[6]; float s = 0.f, ss = 0.f;
#pragma unroll
            for (int j = 0; j < 6; j++) { v[j] = xr[lane + 32 * j]; s += v[j]; ss += v[j] * v[j]; }
#pragma unroll
            for (int o = 16; o > 0; o >>= 1) {
                s  += __shfl_xor_sync(0xffffffffu, s,  o);
                ss += __shfl_xor_sync(0xffffffffu, ss, o);
            }
            float mean = s * (1.f / 192.f);
            float rinv = rsqrtf(ss * (1.f / 192.f) - mean * mean + 1e-5f);
#pragma unroll
            for (int j = 0; j < 6; j++) {
                int k = lane + 32 * j;
                xwh[n * XW_STRH + k] = __float2half((v[j] - mean) * rinv * n1w[k] + n1b[k]);
            }
        } else {
#pragma unroll
            for (int j = 0; j < 3; j++) xwu[n * 100 + lane + 32 * j] = 0u;
        }
    }
    __syncthreads();

    // ---- Phase 2: QKV, uint4 B-fragments from gmem; stmatrix epilogues ----
    for (int p = 0; p < 3; p++) {
        float4 acc[2][6];
#pragma unroll
        for (int mf = 0; mf < 2; mf++)
#pragma unroll
            for (int t = 0; t < 6; t++) acc[mf][t] = make_float4(0.f, 0.f, 0.f, 0.f);

        const int sb = (24 * p + 6 * wn) * 6;
        uint4 bn[6];
#pragma unroll
        for (int tp = 0; tp < 6; tp++)
            bn[tp] = *(const uint4*)(g_qkvF + (size_t)(sb + tp * 6) * 128 + 4 * lane);

#pragma unroll
        for (int kc = 0; kc < 6; kc++) {
            uint4 bc[6];
#pragma unroll
            for (int tp = 0; tp < 6; tp++) bc[tp] = bn[tp];
            if (kc < 5) {
#pragma unroll
                for (int tp = 0; tp < 6; tp++)
                    bn[tp] = *(const uint4*)(g_qkvF + (size_t)(sb + tp * 6 + kc + 1) * 128 + 4 * lane);
            } else if (p < 2) {
                const int sb2 = (24 * (p + 1) + 6 * wn) * 6;
#pragma unroll
                for (int tp = 0; tp < 6; tp++)
                    bn[tp] = *(const uint4*)(g_qkvF + (size_t)(sb2 + tp * 6) * 128 + 4 * lane);
            }
#pragma unroll
            for (int ss = 0; ss < 2; ss++) {
                uint32_t a[2][4];
                ldsm4(a[0][0], a[0][1], a[0][2], a[0][3], aBase + 64 * kc + 32 * ss);
                ldsm4(a[1][0], a[1][1], a[1][2], a[1][3], aBase + 6400 + 64 * kc + 32 * ss);
#pragma unroll
                for (int tp = 0; tp < 6; tp++) {
                    uint32_t b0 = ss ? bc[tp].z : bc[tp].x;
                    uint32_t b1 = ss ? bc[tp].w : bc[tp].y;
#pragma unroll
                    for (int mf = 0; mf < 2; mf++)
                        mma16(acc[mf][tp], a[mf][0], a[mf][1], a[mf][2], a[mf][3], b0, b1);
                }
            }
        }
        // epilogue via stmatrix: all 64 rows stored (garbage masked downstream)
#pragma unroll
        for (int mf = 0; mf < 2; mf++) {
#pragma unroll
            for (int tp = 0; tp < 3; tp++) {
                int t0c = 2 * tp, t1c = 2 * tp + 1;
                int c0 = 48 * wn + 8 * t0c + 2 * q;
                int c1 = 48 * wn + 8 * t1c + 2 * q;
                int j0 = 192 * p + c0, j1 = 192 * p + c1;
                float b00 = __ldg(qkv_b + j0), b01 = __ldg(qkv_b + j0 + 1);
                float b10 = __ldg(qkv_b + j1), b11 = __ldg(qkv_b + j1 + 1);
                float s0 = (p == 0) ? SCALE : 1.f;
                uint32_t v00 = packh2((acc[mf][t0c].x + b00) * s0, (acc[mf][t0c].y + b01) * s0);
                uint32_t v01 = packh2((acc[mf][t0c].z + b00) * s0, (acc[mf][t0c].w + b01) * s0);
                uint32_t v10 = packh2((acc[mf][t1c].x + b10) * s0, (acc[mf][t1c].y + b11) * s0);
                uint32_t v11 = packh2((acc[mf][t1c].z + b10) * s0, (acc[mf][t1c].w + b11) * s0);
                if (p < 2) {
                    int row = 32 * wm + 16 * mf + ((tl & 1) << 3) + rw;
                    int col = 192 * p + 48 * wn + 8 * t0c + 8 * (tl >> 1);
                    stsm4(smaddr(qkh + row * QK_STRH + col), v00, v01, v10, v11);
                } else {
                    int dimrow = 48 * wn + 8 * t0c + 8 * (tl >> 1) + rw;
                    int keyoff = 32 * wm + 16 * mf + ((tl & 1) << 3);
                    stsm4t(smaddr(vth + dimrow * VT_STRH + keyoff), v00, v01, v10, v11);
                }
            }
        }
    }
    __syncthreads();

    // ---- Phase 3: mma attention, 24 units, 3 per warp ----
    {
#pragma unroll 1
        for (int t = 0; t < 3; t++) {
            const int u = warp * 3 + t;
            const int h = u >> 2;
            const int i = u & 3;
            const __half* bias = g_bias + ((size_t)(w * NHEAD + h)) * 64 * 56;
            const uint32_t kBase = smaddr(qkh + lr * QK_STRH + 192 + h * 32 + 8 * (lane >> 3));
            const uint32_t vBase = smaddr(vth + (h * 32 + lr) * VT_STRH + 8 * (lane >> 3));
            const int r0i = 16 * i + g, r1i = r0i + 8;

            float2 bb0[7], bb1[7];
#pragma unroll
            for (int j = 0; j < 7; j++) {
                bb0[j] = __half22float2(*(const __half2*)(bias + r0i * 56 + 8 * j + 2 * q));
                bb1[j] = __half22float2(*(const __half2*)(bias + r1i * 56 + 8 * j + 2 * q));
            }

            uint32_t qA = smaddr(qkh + (16 * i + lr + 8 * lb8) * QK_STRH + h * 32 + 8 * lb16);
            uint32_t aq[2][4];
            ldsm4(aq[0][0], aq[0][1], aq[0][2], aq[0][3], qA);
            ldsm4(aq[1][0], aq[1][1], aq[1][2], aq[1][3], qA + 32);
            float4 S[7];
#pragma unroll
            for (int j = 0; j < 7; j++) {
                S[j] = make_float4(0.f, 0.f, 0.f, 0.f);
                uint32_t b0, b1, b2, b3;
                ldsm4(b0, b1, b2, b3, kBase + j * (8 * QK_STRH * 2));
                mma16(S[j], aq[0][0], aq[0][1], aq[0][2], aq[0][3], b0, b1);
                mma16(S[j], aq[1][0], aq[1][1], aq[1][2], aq[1][3], b2, b3);
                S[j].x += bb0[j].x; S[j].y += bb0[j].y;
                S[j].z += bb1[j].x; S[j].w += bb1[j].y;
            }
            float mx0 = -1e30f, mx1 = -1e30f;
#pragma unroll
            for (int j = 0; j < 7; j++) {
                mx0 = fmaxf(mx0, fmaxf(S[j].x, S[j].y));
                mx1 = fmaxf(mx1, fmaxf(S[j].z, S[j].w));
            }
#pragma unroll
            for (int o = 1; o < 4; o <<= 1) {
                mx0 = fmaxf(mx0, __shfl_xor_sync(0xffffffffu, mx0, o));
                mx1 = fmaxf(mx1, __shfl_xor_sync(0xffffffffu, mx1, o));
            }
            float sum0 = 0.f, sum1 = 0.f;
#pragma unroll
            for (int j = 0; j < 7; j++) {
                S[j].x = __expf(S[j].x - mx0); S[j].y = __expf(S[j].y - mx0);
                S[j].z = __expf(S[j].z - mx1); S[j].w = __expf(S[j].w - mx1);
                sum0 += S[j].x + S[j].y; sum1 += S[j].z + S[j].w;
            }
#pragma unroll
            for (int o = 1; o < 4; o <<= 1) {
                sum0 += __shfl_xor_sync(0xffffffffu, sum0, o);
                sum1 += __shfl_xor_sync(0xffffffffu, sum1, o);
            }
            float rc0 = 1.f / sum0, rc1 = 1.f / sum1;
            uint32_t pa[4][4];
#pragma unroll
            for (int kk = 0; kk < 3; kk++) {
                pa[kk][0] = packh2(S[2 * kk].x, S[2 * kk].y);
                pa[kk][1] = packh2(S[2 * kk].z, S[2 * kk].w);
                pa[kk][2] = packh2(S[2 * kk + 1].x, S[2 * kk + 1].y);
                pa[kk][3] = packh2(S[2 * kk + 1].z, S[2 * kk + 1].w);
            }
            pa[3][0] = packh2(S[6].x, S[6].y);
            pa[3][1] = packh2(S[6].z, S[6].w);
            pa[3][2] = 0u; pa[3][3] = 0u;
            float4 O[4];
#pragma unroll
            for (int vj = 0; vj < 4; vj++) {
                O[vj] = make_float4(0.f, 0.f, 0.f, 0.f);
                uint32_t va0, va1, va2, va3, vb0, vb1, vb2, vb3;
                ldsm4(va0, va1, va2, va3, vBase + vj * (8 * VT_STRH * 2));
                ldsm4(vb0, vb1, vb2, vb3, vBase + vj * (8 * VT_STRH * 2) + 64);
                mma16(O[vj], pa[0][0], pa[0][1], pa[0][2], pa[0][3], va0, va1);
                mma16(O[vj], pa[1][0], pa[1][1], pa[1][2], pa[1][3], va2, va3);
                mma16(O[vj], pa[2][0], pa[2][1], pa[2][2], pa[2][3], vb0, vb1);
                mme_dummy:;
                mma16(O[vj], pa[3][0], pa[3][1], pa[3][2], pa[3][3], vb2, vb3);
            }
            // store all rows via stmatrix (garbage rows discarded by proj epilogue)
#pragma unroll
            for (int vjp = 0; vjp < 2; vjp++) {
                uint32_t v0 = packh2(O[2 * vjp].x * rc0, O[2 * vjp].y * rc0);
                uint32_t v1 = packh2(O[2 * vjp].z * rc1, O[2 * vjp].w * rc1);
                uint32_t v2 = packh2(O[2 * vjp + 1].x * rc0, O[2 * vjp + 1].y * rc0);
                uint32_t v3 = packh2(O[2 * vjp + 1].z * rc1, O[2 * vjp + 1].w * rc1);
                int row = 16 * i + ((tl & 1) << 3) + rw;
                int col = h * 32 + 16 * vjp + 8 * (tl >> 1);
                stsm4(smaddr(xwh + row * XW_STRH + col), v0, v1, v2, v3);
            }
        }
    }
    __syncthreads();

    // ---- Phase 4: proj, uint4 B-fragments, guarded residual scatter ----
    {
        float4 acc[2][6];
#pragma unroll
        for (int mf = 0; mf < 2; mf++)
#pragma unroll
            for (int t = 0; t < 6; t++) acc[mf][t] = make_float4(0.f, 0.f, 0.f, 0.f);

        const int sb = (6 * wn) * 6;
        uint4 bn[6];
#pragma unroll
        for (int tp = 0; tp < 6; tp++)
            bn[tp] = *(const uint4*)(g_projF + (size_t)(sb + tp * 6) * 128 + 4 * lane);

#pragma unroll
        for (int kc = 0; kc < 6; kc++) {
            uint4 bc[6];
#pragma unroll
            for (int tp = 0; tp < 6; tp++) bc[tp] = bn[tp];
            if (kc < 5) {
#pragma unroll
                for (int tp = 0; tp < 6; tp++)
                    bn[tp] = *(const uint4*)(g_projF + (size_t)(sb + tp * 6 + kc + 1) * 128 + 4 * lane);
            }
#pragma unroll
            for (int ss = 0; ss < 2; ss++) {
                uint32_t a[2][4];
                ldsm4(a[0][0], a[0][1], a[0][2], a[0][3], aBase + 64 * kc + 32 * ss);
                ldsm4(a[1][0], a[1][1], a[1][2], a[1][3], aBase + 6400 + 64 * kc + 32 * ss);
#pragma unroll
                for (int tp = 0; tp < 6; tp++) {
                    uint32_t b0 = ss ? bc[tp].z : bc[tp].x;
                    uint32_t b1 = ss ? bc[tp].w : bc[tp].y;
#pragma unroll
                    for (int mf = 0; mf < 2; mf++)
                        mma16(acc[mf][tp], a[mf][0], a[mf][1], a[mf][2], a[mf][3], b0, b1);
                }
            }
        }

#pragma unroll
        for (int mf = 0; mf < 2; mf++) {
            int r0 = 32 * wm + 16 * mf + g;
            bool u0 = r0 < NT, u1 = (r0 + 8) < NT;
            size_t base0 = 0, base1 = 0;
            if (u0) {
                int gr = wh * 7 + r0 / 7 + 3; if (gr >= 56) gr -= 56;
                int gc = ww * 7 + r0 % 7 + 3; if (gc >= 56) gc -= 56;
                base0 = ((size_t)b * 3136 + gr * 56 + gc) * Cc;
            }
            if (u1) {
                int r1 = r0 + 8;
                int gr = wh * 7 + r1 / 7 + 3; if (gr >= 56) gr -= 56;
                int gc = ww * 7 + r1 % 7 + 3; if (gc >= 56) gc -= 56;
                base1 = ((size_t)b * 3136 + gr * 56 + gc) * Cc;
            }
#pragma unroll
            for (int t = 0; t < 6; t++) {
                int col = 48 * wn + 8 * t + 2 * q;
                float pb0 = __ldg(proj_b + col), pb1 = __ldg(proj_b + col + 1);
                if (u0) {
                    float2 xv = *(const float2*)(x + base0 + col);
                    float2 r; r.x = xv.x + acc[mf][t].x + pb0; r.y = xv.y + acc[mf][t].y + pb1;
                    *(float2*)(g_x2 + base0 + col) = r;
                }
                if (u1) {
                    float2 xv = *(const float2*)(x + base1 + col);
                    float2 r; r.x = xv.x + acc[mf][t].z + pb0; r.y = xv.y + acc[mf][t].w + pb1;
                    *(float2*)(g_x2 + base1 + col) = r;
                }
            }
        }
    }

    __threadfence();
    __syncthreads();
    if (tid == 0) atomicAdd(&g_dep[b * 8 + wh], 1);
}

__device__ __forceinline__ void mlp_body(
    __half* smh, int m,
    const float* __restrict__ n2w, const float* __restrict__ n2b,
    const float* __restrict__ fc1b, const float* __restrict__ fc2b,
    float* __restrict__ out)
{
    __half* xnh = smh;                       // [64][200]
    __half* hsh = smh + OFF_HS_H;            // [64][136]

    const int tid  = threadIdx.x;
    const int warp = tid >> 5;
    const int lane = tid & 31;
    const int g    = lane >> 2;
    const int q    = lane & 3;
    const int wm   = warp & 1;      // fc2 m-half
    const int wn   = warp >> 1;     // fc2 n-quarter (48 cols)
    const int wm1  = warp >> 2;     // fc1 m-half (32 rows)
    const int wn1  = warp & 3;      // fc1 n-32 block within 128-chunk
    const int lr   = lane & 7;
    const int lb8  = (lane >> 3) & 1;
    const int lb16 = lane >> 4;
    const int tl   = lane >> 3;
    const int rw   = lane & 7;
    const size_t t0 = (size_t)m * 64;

    const uint32_t aBase1 = smaddr(xnh + (32 * wm1 + lr + 8 * lb8) * XW_STRH + 8 * lb16);
    const uint32_t aBase2 = smaddr(hsh + (32 * wm + lr + 8 * lb8) * HS_STRH + 8 * lb16);

    // ---- acquire ----
    {
        int mm = m % 49;
        int bb = m / 49;
        int gr0 = (mm * 64) / 56;
        int gr1 = (mm * 64 + 63) / 56;
        int i0 = bb * 8 + ((gr0 + 53) % 56) / 7;
        int i1 = bb * 8 + ((gr1 + 53) % 56) / 7;
        if (tid == 0) {
            while (atomicAdd(&g_dep[i0], 0) < 8 || atomicAdd(&g_dep[i1], 0) < 8)
                __nanosleep(100);
        }
        __syncthreads();
    }

    // ---- LN2 ----
    for (int n = warp; n < 64; n += 8) {
        const float* xr = g_x2 + (t0 + n) * Cc;
        float v[6]; float s = 0.f, ss = 0.f;
#pragma unroll
        for (int j = 0; j < 6; j++) { v[j] = xr[lane + 32 * j]; s += v[j]; ss += v[j] * v[j]; }
#pragma unroll
        for (int o = 16; o > 0; o >>= 1) {
            s  += __shfl_xor_sync(0xffffffffu, s,  o);
            ss += __shfl_xor_sync(0xffffffffu, ss, o);
        }
        float mean = s * (1.f / 192.f);
        float rinv = rsqrtf(ss * (1.f / 192.f) - mean * mean + 1e-5f);
#pragma unroll
        for (int j = 0; j < 6; j++) {
            int k = lane + 32 * j;
            xnh[n * XW_STRH + k] = __float2half((v[j] - mean) * rinv * n2w[k] + n2b[k]);
        }
    }
    __syncthreads();

    float4 yacc[2][6];
#pragma unroll
    for (int mf = 0; mf < 2; mf++)
#pragma unroll
        for (int t = 0; t < 6; t++) yacc[mf][t] = make_float4(0.f, 0.f, 0.f, 0.f);

    for (int hc = 0; hc < HIDDEN; hc += 128) {
        // ---- fc1: H(64x128) = xn @ w1chunk ; warp tile m32 x n32 ----
        float4 acc1[2][4];
#pragma unroll
        for (int mf = 0; mf < 2; mf++)
#pragma unroll
            for (int t = 0; t < 4; t++) acc1[mf][t] = make_float4(0.f, 0.f, 0.f, 0.f);

        const int sb1 = ((hc >> 3) + 4 * wn1) * 6;
        uint4 b1n[4];
#pragma unroll
        for (int t = 0; t < 4; t++)
            b1n[t] = *(const uint4*)(g_fc1F + (size_t)(sb1 + t * 6) * 128 + 4 * lane);

#pragma unroll
        for (int kc = 0; kc < 6; kc++) {
            uint4 b1c[4];
#pragma unroll
            for (int t = 0; t < 4; t++) b1c[t] = b1n[t];
            if (kc < 5) {
#pragma unroll
                for (int t = 0; t < 4; t++)
                    b1n[t] = *(const uint4*)(g_fc1F + (size_t)(sb1 + t * 6 + kc + 1) * 128 + 4 * lane);
            }
#pragma unroll
            for (int ss = 0; ss < 2; ss++) {
                uint32_t a[2][4];
                ldsm4(a[0][0], a[0][1], a[0][2], a[0][3], aBase1 + 64 * kc + 32 * ss);
                ldsm4(a[1][0], a[1][1], a[1][2], a[1][3], aBase1 + 6400 + 64 * kc + 32 * ss);
#pragma unroll
                for (int t = 0; t < 4; t++) {
                    uint32_t b0 = ss ? b1c[t].z : b1c[t].x;
                    uint32_t b1 = ss ? b1c[t].w : b1c[t].y;
#pragma unroll
                    for (int mf = 0; mf < 2; mf++)
                        mma16(acc1[mf][t], a[mf][0], a[mf][1], a[mf][2], a[mf][3], b0, b1);
                }
            }
        }

        // prefetch fc2 first k32 of this chunk
        const int t2k = hc >> 5;
        uint4 b2n[6];
#pragma unroll
        for (int tp = 0; tp < 6; tp++)
            b2n[tp] = *(const uint4*)(g_fc2F + (size_t)((6 * wn + tp) * 24 + t2k) * 128 + 4 * lane);

        __syncthreads();   // previous fc2 done reading hs
        // bias + gelu -> hs via stmatrix
#pragma unroll
        for (int mf = 0; mf < 2; mf++) {
#pragma unroll
            for (int tp = 0; tp < 2; tp++) {
                int t0c = 2 * tp, t1c = 2 * tp + 1;
                int c0 = 32 * wn1 + 8 * t0c + 2 * q;
                int c1 = 32 * wn1 + 8 * t1c + 2 * q;
                float b00 = __ldg(fc1b + hc + c0), b01 = __ldg(fc1b + hc + c0 + 1);
                float b10 = __ldg(fc1b + hc + c1), b11 = __ldg(fc1b + hc + c1 + 1);
                uint32_t v0 = packh2(gelu_exact(acc1[mf][t0c].x + b00),
                                     gelu_exact(acc1[mf][t0c].y + b01));
                uint32_t v1 = packh2(gelu_exact(acc1[mf][t0c].z + b00),
                                     gelu_exact(acc1[mf][t0c].w + b01));
                uint32_t v2 = packh2(gelu_exact(acc1[mf][t1c].x + b10),
                                     gelu_exact(acc1[mf][t1c].y + b11));
                uint32_t v3 = packh2(gelu_exact(acc1[mf][t1c].z + b10),
                                     gelu_exact(acc1[mf][t1c].w + b11));
                int row = 32 * wm1 + 16 * mf + ((tl & 1) << 3) + rw;
                int col = 32 * wn1 + 8 * t0c + 8 * (tl >> 1);
                stsm4(smaddr(hsh + row * HS_STRH + col), v0, v1, v2, v3);
            }
        }
        __syncthreads();   // hs ready

        // ---- fc2: Y += H @ w2chunk ; warp tile m32 x n48, 4 k32 steps ----
#pragma unroll
        for (int kc = 0; kc < 4; kc++) {
            uint4 b2c[6];
#pragma unroll
            for (int tp = 0; tp < 6; tp++) b2c[tp] = b2n[tp];
            if (kc < 3) {
#pragma unroll
                for (int tp = 0; tp < 6; tp++)
                    b2n[tp] = *(const uint4*)(g_fc2F + (size_t)((6 * wn + tp) * 24 + t2k + kc + 1) * 128 + 4 * lane);
            }
#pragma unroll
            for (int ss = 0; ss < 2; ss++) {
                uint32_t a[2][4];
                ldsm4(a[0][0], a[0][1], a[0][2], a[0][3], aBase2 + 64 * kc + 32 * ss);
                ldsm4(a[1][0], a[1][1], a[1][2], a[1][3], aBase2 + 4352 + 64 * kc + 32 * ss);
#pragma unroll
                for (int tp = 0; tp < 6; tp++) {
                    uint32_t b0 = ss ? b2c[tp].z : b2c[tp].x;
                    uint32_t b1 = ss ? b2c[tp].w : b2c[tp].y;
#pragma unroll
                    for (int mf = 0; mf < 2; mf++)
                        mma16(yacc[mf][tp], a[mf][0], a[mf][1], a[mf][2], a[mf][3], b0, b1);
                }
            }
        }
    }

#pragma unroll
    for (int mf = 0; mf < 2; mf++) {
        int r0 = 32 * wm + 16 * mf + g;
#pragma unroll
        for (int t = 0; t < 6; t++) {
            int col = 48 * wn + 8 * t + 2 * q;
            float b0v = __ldg(fc2b + col), b1v = __ldg(fc2b + col + 1);
            {
                size_t base = (t0 + r0) * Cc + col;
                float2 xv = *(const float2*)(g_x2 + base);
                float2 r; r.x = xv.x + yacc[mf][t].x + b0v; r.y = xv.y + yacc[mf][t].y + b1v;
                *(float2*)(out + base) = r;
            }
            {
                size_t base = (t0 + r0 + 8) * Cc + col;
                float2 xv = *(const float2*)(g_x2 + base);
                float2 r; r.x = xv.x + yacc[mf][t].z + b0v; r.y = xv.y + yacc[mf][t].w + b1v;
                *(float2*)(out + base) = r;
            }
        }
    }
}

__global__ __launch_bounds__(256, 2) void swin_fused_kernel(
    const float* __restrict__ x,
    const float* __restrict__ qkv_b, const float* __restrict__ proj_b,
    const float* __restrict__ n1w, const float* __restrict__ n1b,
    const float* __restrict__ n2w, const float* __restrict__ n2b,
    const float* __restrict__ fc1b, const float* __restrict__ fc2b,
    float* __restrict__ out)
{
    extern __shared__ __half smh[];
    const int bid = blockIdx.x;
    if (bid < ATTN_BLOCKS) {
        attn_body(smh, bid, x, qkv_b, proj_b, n1w, n1b);
    } else {
        mlp_body(smh, bid - ATTN_BLOCKS, n2w, n2b, fc1b, fc2b, out);
    }
}

// ---------------------------------------------------------------------------
extern "C" void kernel_launch(void* const* d_in, const int* in_sizes, int n_in,
                              void* d_out, int out_size)
{
    const float* x      = (const float*)d_in[0];
    const float* mask   = (const float*)d_in[1];
    const float* rel    = (const float*)d_in[2];
    const float* qkv_w  = (const float*)d_in[3];
    const float* qkv_b  = (const float*)d_in[4];
    const float* proj_w = (const float*)d_in[5];
    const float* proj_b = (const float*)d_in[6];
    const float* n1w    = (const float*)d_in[7];
    const float* n1b    = (const float*)d_in[8];
    const float* n2w    = (const float*)d_in[9];
    const float* n2b    = (const float*)d_in[10];
    const float* fc1w   = (const float*)d_in[11];
    const float* fc1b   = (const float*)d_in[12];
    const float* fc2w   = (const float*)d_in[13];
    const float* fc2b   = (const float*)d_in[14];
    float* out = (float*)d_out;

    cudaFuncSetAttribute(swin_fused_kernel, cudaFuncAttributeMaxDynamicSharedMemorySize,
                         FUSED_SM_BYTES);

    convert_w<<<1184, 256>>>(qkv_w, proj_w, fc1w, fc2w, mask, rel);
    swin_fused_kernel<<<ATTN_BLOCKS + MLP_BLOCKS, 256, FUSED_SM_BYTES>>>(
        x, qkv_b, proj_b, n1w, n1b, n2w, n2b, fc1b, fc2b, out);
}